// round 1
// baseline (speedup 1.0000x reference)
#include <cuda_runtime.h>
#include <math.h>

#define DEV_INLINE __device__ __forceinline__

// ---------------- problem constants ----------------
constexpr int cB = 2, cN = 512, cF = 1024, cH = 4, cDH = 256;
constexpr int cAH = 256, cHID = 512, cOUT = 128, cNC = 10;
constexpr int NN = cN * cN;               // 262144
constexpr int KSEL = 209715;              // int(0.8 * 512 * 512)
constexpr int RANK_SEL = NN - KSEL;       // 52429 : 0-indexed ascending order stat

// ---------------- scratch layout (one big device buffer) ----------------
constexpr size_t OFF_HP    = 0;
constexpr size_t OFF_ALPHA = OFF_HP    + (size_t)cB * cN * cF;       // 1,048,576
constexpr size_t OFF_NF    = OFF_ALPHA + (size_t)cB * cH * cN * cN;  // +2,097,152
constexpr size_t OFF_PI    = OFF_NF    + (size_t)cB * cN * cF;
constexpr size_t OFF_PJ    = OFF_PI    + (size_t)cB * cN * cAH;
constexpr size_t OFF_ES    = OFF_PJ    + (size_t)cB * cN * cAH;
constexpr size_t OFF_SM    = OFF_ES    + (size_t)cB * NN;
constexpr size_t OFF_ADJ   = OFF_SM    + (size_t)cB * NN;
constexpr size_t OFF_H1    = OFF_ADJ   + (size_t)cB * NN;
constexpr size_t OFF_G1    = OFF_H1    + (size_t)cB * cN * cF;
constexpr size_t OFF_H2    = OFF_G1    + (size_t)cB * cN * cHID;
constexpr size_t OFF_G2    = OFF_H2    + (size_t)cB * cN * cHID;
constexpr size_t OFF_SI    = OFF_G2    + (size_t)cB * cN * cOUT;
constexpr size_t OFF_SJ    = OFF_SI    + (size_t)cB * cH * cN;
constexpr size_t OFF_PART  = OFF_SJ    + (size_t)cB * cH * cN;
constexpr size_t OFF_RED   = OFF_PART  + (size_t)cB * 128;
constexpr size_t OFF_BN1   = OFF_RED   + (size_t)cB * 8;
constexpr size_t OFF_BN2   = OFF_BN1   + (size_t)2 * cHID;
constexpr size_t BUF_TOTAL = OFF_BN2   + (size_t)2 * cOUT;

__device__ float    g_buf[BUF_TOTAL];
__device__ unsigned g_hist[cB * 256];
__device__ unsigned g_prefix[cB];
__device__ int      g_rank[cB];

// ---------------- reductions ----------------
struct SumOp { DEV_INLINE float operator()(float a, float b) const { return a + b; } };
struct MaxOp { DEV_INLINE float operator()(float a, float b) const { return fmaxf(a, b); } };

template <typename Op>
DEV_INLINE float blockReduceF(float v, Op op, float init) {
    __shared__ float sh[32];
    __syncthreads();  // protect sh reuse across successive calls
    int lane = threadIdx.x & 31, w = threadIdx.x >> 5;
#pragma unroll
    for (int o = 16; o; o >>= 1) v = op(v, __shfl_down_sync(0xffffffffu, v, o));
    if (lane == 0) sh[w] = v;
    __syncthreads();
    int nw = (blockDim.x + 31) >> 5;
    v = (threadIdx.x < nw) ? sh[threadIdx.x] : init;
    if (w == 0) {
#pragma unroll
        for (int o = 16; o; o >>= 1) v = op(v, __shfl_down_sync(0xffffffffu, v, o));
        if (lane == 0) sh[0] = v;
    }
    __syncthreads();
    return sh[0];
}

DEV_INLINE double blockReduceD(double v) {
    __shared__ double shd[32];
    __syncthreads();
    int lane = threadIdx.x & 31, w = threadIdx.x >> 5;
#pragma unroll
    for (int o = 16; o; o >>= 1) v += __shfl_down_sync(0xffffffffu, v, o);
    if (lane == 0) shd[w] = v;
    __syncthreads();
    int nw = (blockDim.x + 31) >> 5;
    v = (threadIdx.x < nw) ? shd[threadIdx.x] : 0.0;
    if (w == 0) {
#pragma unroll
        for (int o = 16; o; o >>= 1) v += __shfl_down_sync(0xffffffffu, v, o);
        if (lane == 0) shd[0] = v;
    }
    __syncthreads();
    return shd[0];
}

// ---------------- GEMM: C[m,n] = sum_k A[m,k]*B[n,k] (+bias[n]) ----------------
// 64x64 tile, TK=16, 256 threads, 4x4 microtile. All dims multiples of 64/16.
__global__ void gemm_nt(const float* __restrict__ A, int lda,
                        const float* __restrict__ Bm, int ldb,
                        float* __restrict__ C, int ldc,
                        int M, int Nd, int K,
                        const float* __restrict__ bias) {
    __shared__ float As[16][65];
    __shared__ float Bs[16][65];
    int tid = threadIdx.x;
    int tx = tid & 15, ty = tid >> 4;
    int m0 = blockIdx.y * 64, n0 = blockIdx.x * 64;
    float acc[4][4] = {};
    for (int k0 = 0; k0 < K; k0 += 16) {
        for (int idx = tid; idx < 64 * 16; idx += 256) {
            int m = idx >> 4, k = idx & 15;
            As[k][m] = A[(size_t)(m0 + m) * lda + k0 + k];
            Bs[k][m] = Bm[(size_t)(n0 + m) * ldb + k0 + k];
        }
        __syncthreads();
#pragma unroll
        for (int k = 0; k < 16; k++) {
            float a[4], b[4];
#pragma unroll
            for (int u = 0; u < 4; u++) a[u] = As[k][ty + 16 * u];
#pragma unroll
            for (int v = 0; v < 4; v++) b[v] = Bs[k][tx + 16 * v];
#pragma unroll
            for (int u = 0; u < 4; u++)
#pragma unroll
                for (int v = 0; v < 4; v++) acc[u][v] += a[u] * b[v];
        }
        __syncthreads();
    }
#pragma unroll
    for (int u = 0; u < 4; u++) {
        int m = m0 + ty + 16 * u;
#pragma unroll
        for (int v = 0; v < 4; v++) {
            int n = n0 + tx + 16 * v;
            float val = acc[u][v];
            if (bias) val += bias[n];
            C[(size_t)m * ldc + n] = val;
        }
    }
}

// ---------------- batched GEMM: C[m,n] = sum_k A[m,k]*B[k,n] ----------------
// z -> (z1 = z/HH, z2 = z%HH); per-operand offsets off = z1*s1 + z2*s2
__global__ void gemm_nn(const float* __restrict__ A, int lda, long long sA1, long long sA2,
                        const float* __restrict__ Bm, int ldb, long long sB1, long long sB2,
                        float* __restrict__ C, int ldc, long long sC1, long long sC2,
                        int M, int Nd, int K, int HH) {
    __shared__ float As[16][65];
    __shared__ float Bs[16][65];
    int z = blockIdx.z;
    int z1 = z / HH, z2 = z % HH;
    A  += (size_t)(z1 * sA1 + z2 * sA2);
    Bm += (size_t)(z1 * sB1 + z2 * sB2);
    C  += (size_t)(z1 * sC1 + z2 * sC2);
    int tid = threadIdx.x;
    int tx = tid & 15, ty = tid >> 4;
    int m0 = blockIdx.y * 64, n0 = blockIdx.x * 64;
    float acc[4][4] = {};
    for (int k0 = 0; k0 < K; k0 += 16) {
        for (int idx = tid; idx < 64 * 16; idx += 256) {
            int m = idx >> 4, k = idx & 15;
            As[k][m] = A[(size_t)(m0 + m) * lda + k0 + k];
        }
        for (int idx = tid; idx < 64 * 16; idx += 256) {
            int k = idx >> 6, n = idx & 63;
            Bs[k][n] = Bm[(size_t)(k0 + k) * ldb + n0 + n];
        }
        __syncthreads();
#pragma unroll
        for (int k = 0; k < 16; k++) {
            float a[4], b[4];
#pragma unroll
            for (int u = 0; u < 4; u++) a[u] = As[k][ty + 16 * u];
#pragma unroll
            for (int v = 0; v < 4; v++) b[v] = Bs[k][tx + 16 * v];
#pragma unroll
            for (int u = 0; u < 4; u++)
#pragma unroll
                for (int v = 0; v < 4; v++) acc[u][v] += a[u] * b[v];
        }
        __syncthreads();
    }
#pragma unroll
    for (int u = 0; u < 4; u++) {
        int m = m0 + ty + 16 * u;
#pragma unroll
        for (int v = 0; v < 4; v++) {
            int n = n0 + tx + 16 * v;
            C[(size_t)m * ldc + n] = acc[u][v];
        }
    }
}

// ---------------- attention scores s_i, s_j ----------------
__global__ void si_sj_kernel(const float* __restrict__ hp, const float* __restrict__ attn_w,
                             float* __restrict__ si, float* __restrict__ sj) {
    int bn = blockIdx.x;
    int b = bn >> 9, n = bn & 511;
    const float* row = hp + (size_t)bn * cF;
    int t = threadIdx.x;  // 256
    for (int h = 0; h < cH; h++) {
        float v = row[h * cDH + t];
        float vi = v * attn_w[h * 2 * cDH + t];
        float vj = v * attn_w[h * 2 * cDH + cDH + t];
        float s1 = blockReduceF(vi, SumOp(), 0.f);
        float s2 = blockReduceF(vj, SumOp(), 0.f);
        if (t == 0) {
            si[((size_t)b * cH + h) * cN + n] = s1;
            sj[((size_t)b * cH + h) * cN + n] = s2;
        }
    }
}

// ---------------- per-row attention softmax (leakyrelu(si+sj)) ----------------
__global__ void attn_softmax(const float* __restrict__ si, const float* __restrict__ sj,
                             float* __restrict__ alpha) {
    int id = blockIdx.x;          // bh*cN + i
    int i = id & 511, bh = id >> 9;
    float s_i = si[(size_t)bh * cN + i];
    const float* sjr = sj + (size_t)bh * cN;
    int t = threadIdx.x;  // 256, 2 j per thread
    float x0 = s_i + sjr[t];
    float x1 = s_i + sjr[t + 256];
    float e0 = x0 >= 0.f ? x0 : 0.2f * x0;
    float e1 = x1 >= 0.f ? x1 : 0.2f * x1;
    float m = blockReduceF(fmaxf(e0, e1), MaxOp(), -1e30f);
    float p0 = expf(e0 - m), p1 = expf(e1 - m);
    float s = blockReduceF(p0 + p1, SumOp(), 0.f);
    float inv = 1.f / s;
    float* arow = alpha + (size_t)id * cN;
    arow[t] = p0 * inv;
    arow[t + 256] = p1 * inv;
}

// ---------------- edge MLP: es[b,i,j] = sum_a relu(pi'+pj)*w2 + b2 ----------------
// pi' already contains +b1 (gemm bias). 64x64 tile, a-chunks of 32.
__global__ void edge_kernel(const float* __restrict__ pi, const float* __restrict__ pj,
                            const float* __restrict__ w2, const float* __restrict__ b2,
                            float* __restrict__ es) {
    __shared__ float pis[32][65];
    __shared__ float pjs[32][65];
    __shared__ float w2s[32];
    int b = blockIdx.z;
    int i0 = blockIdx.y * 64, j0 = blockIdx.x * 64;
    int tid = threadIdx.x;
    int tx = tid & 15, ty = tid >> 4;
    float acc[4][4] = {};
    for (int a0 = 0; a0 < cAH; a0 += 32) {
        for (int idx = tid; idx < 64 * 32; idx += 256) {
            int a = idx & 31, r = idx >> 5;
            pis[a][r] = pi[((size_t)(b * cN + i0 + r)) * cAH + a0 + a];
            pjs[a][r] = pj[((size_t)(b * cN + j0 + r)) * cAH + a0 + a];
        }
        if (tid < 32) w2s[tid] = w2[a0 + tid];
        __syncthreads();
#pragma unroll 8
        for (int a = 0; a < 32; a++) {
            float w = w2s[a];
            float pv[4], qv[4];
#pragma unroll
            for (int u = 0; u < 4; u++) pv[u] = pis[a][ty + 16 * u];
#pragma unroll
            for (int v = 0; v < 4; v++) qv[v] = pjs[a][tx + 16 * v];
#pragma unroll
            for (int u = 0; u < 4; u++)
#pragma unroll
                for (int v = 0; v < 4; v++)
                    acc[u][v] += fmaxf(pv[u] + qv[v], 0.f) * w;
        }
        __syncthreads();
    }
    float bb = b2[0];
#pragma unroll
    for (int u = 0; u < 4; u++)
#pragma unroll
        for (int v = 0; v < 4; v++)
            es[((size_t)b * cN + i0 + ty + 16 * u) * cN + j0 + tx + 16 * v] = acc[u][v] + bb;
}

// ---------------- flat softmax (scale 1/TEMP = 2) ----------------
__global__ void pmax_kernel(const float* __restrict__ es, float* __restrict__ part) {
    int b = blockIdx.y, seg = blockIdx.x;  // 128 segs of 2048
    const float* p = es + (size_t)b * NN + seg * 2048;
    float m = -1e30f;
    for (int i = threadIdx.x; i < 2048; i += 256) m = fmaxf(m, p[i]);
    m = blockReduceF(m, MaxOp(), -1e30f);
    if (threadIdx.x == 0) part[b * 128 + seg] = m;
}

__global__ void psum_kernel(const float* __restrict__ es, const float* __restrict__ red,
                            float* __restrict__ part) {
    int b = blockIdx.y, seg = blockIdx.x;
    float m = red[b * 8 + 0];
    const float* p = es + (size_t)b * NN + seg * 2048;
    float s = 0.f;
    for (int i = threadIdx.x; i < 2048; i += 256) s += expf(2.f * (p[i] - m));
    s = blockReduceF(s, SumOp(), 0.f);
    if (threadIdx.x == 0) part[b * 128 + seg] = s;
}

__global__ void reduce_part(const float* __restrict__ part, float* __restrict__ red,
                            int mode /*0 max,1 sum*/, int slot) {
    int b = blockIdx.x;
    float v = part[b * 128 + threadIdx.x];  // 128 threads
    v = mode ? blockReduceF(v, SumOp(), 0.f) : blockReduceF(v, MaxOp(), -1e30f);
    if (threadIdx.x == 0) red[b * 8 + slot] = v;
}

__global__ void softmax_write(const float* __restrict__ es, const float* __restrict__ red,
                              float* __restrict__ sm) {
    size_t i = (size_t)blockIdx.x * blockDim.x + threadIdx.x;
    int b = (int)(i / NN);
    float m = red[b * 8 + 0];
    float inv = 1.f / red[b * 8 + 1];
    sm[i] = expf(2.f * (es[i] - m)) * inv;
}

// ---------------- exact radix select (positive floats, MSB-first) ----------------
__global__ void sel_init() {
    int t = blockIdx.x * blockDim.x + threadIdx.x;
    if (t < cB * 256) g_hist[t] = 0;
    if (t < cB) { g_prefix[t] = 0; g_rank[t] = RANK_SEL; }
}

__global__ void sel_hist(const float* __restrict__ sm, int pass) {
    int b = blockIdx.y;
    int shift = 24 - 8 * pass;
    unsigned prefix = g_prefix[b];
    __shared__ unsigned hist[256];
    hist[threadIdx.x] = 0;
    __syncthreads();
    const unsigned* data = reinterpret_cast<const unsigned*>(sm) + (size_t)b * NN;
    int per = NN / gridDim.x;
    int base = blockIdx.x * per;
    for (int i = threadIdx.x; i < per; i += 256) {
        unsigned u = data[base + i];
        bool ok = (pass == 0) || ((u >> (shift + 8)) == (prefix >> (shift + 8)));
        int bin = ok ? (int)((u >> shift) & 255u) : -1;
        unsigned mask = __match_any_sync(0xffffffffu, bin);
        if (bin >= 0 && ((threadIdx.x & 31) == (__ffs(mask) - 1)))
            atomicAdd(&hist[bin], (unsigned)__popc(mask));
    }
    __syncthreads();
    if (hist[threadIdx.x]) atomicAdd(&g_hist[b * 256 + threadIdx.x], hist[threadIdx.x]);
}

__global__ void sel_step(float* __restrict__ red, int pass) {
    int b = blockIdx.x;
    int shift = 24 - 8 * pass;
    if (threadIdx.x == 0) {
        int r = g_rank[b];
        unsigned cum = 0;
        int sel = 0;
        for (int x = 0; x < 256; x++) {
            unsigned h = g_hist[b * 256 + x];
            if (cum + h > (unsigned)r) { sel = x; break; }
            cum += h;
        }
        g_rank[b] = r - (int)cum;
        unsigned p = g_prefix[b] | ((unsigned)sel << shift);
        g_prefix[b] = p;
        if (pass == 3) red[b * 8 + 2] = __uint_as_float(p);
    }
    __syncthreads();
    g_hist[b * 256 + threadIdx.x] = 0;  // reset for next pass
}

__global__ void csum_kernel(const float* __restrict__ sm, const float* __restrict__ red,
                            float* __restrict__ part) {
    int b = blockIdx.y, seg = blockIdx.x;
    float thr = red[b * 8 + 2];
    const float* p = sm + (size_t)b * NN + seg * 2048;
    float s = 0.f;
    for (int i = threadIdx.x; i < 2048; i += 256) {
        float v = p[i];
        if (v >= thr) s += v;
    }
    s = blockReduceF(s, SumOp(), 0.f);
    if (threadIdx.x == 0) part[b * 128 + seg] = s;
}

__global__ void adj_write(const float* __restrict__ sm, const float* __restrict__ red,
                          float* __restrict__ adj) {
    size_t i = (size_t)blockIdx.x * blockDim.x + threadIdx.x;
    int b = (int)(i / NN);
    float thr = red[b * 8 + 2];
    float inv = 1.f / (red[b * 8 + 3] + 1e-12f);
    float v = sm[i];
    adj[i] = (v >= thr) ? v * inv : 0.f;
}

// ---------------- batchnorm ----------------
__global__ void bn_stats(const float* __restrict__ h, int C, float* __restrict__ stats) {
    int c = blockIdx.x;
    double s = 0.0, s2 = 0.0;
    for (int r = threadIdx.x; r < cB * cN; r += blockDim.x) {
        double v = (double)h[(size_t)r * C + c];
        s += v;
        s2 += v * v;
    }
    s = blockReduceD(s);
    s2 = blockReduceD(s2);
    if (threadIdx.x == 0) {
        double m = s / (cB * cN);
        double var = s2 / (cB * cN) - m * m;
        stats[2 * c] = (float)m;
        stats[2 * c + 1] = (float)rsqrt(var + 1e-5);
    }
}

__global__ void bn_relu(const float* __restrict__ h, const float* __restrict__ stats,
                        const float* __restrict__ gamma, const float* __restrict__ beta,
                        float* __restrict__ out, int C) {
    size_t i = (size_t)blockIdx.x * blockDim.x + threadIdx.x;
    int c = (int)(i % C);
    float v = (h[i] - stats[2 * c]) * stats[2 * c + 1] * gamma[c] + beta[c];
    out[i] = fmaxf(v, 0.f);
}

// ---------------- final: bn2 + relu + mean over N + classifier ----------------
__global__ void final_kernel(const float* __restrict__ g2, const float* __restrict__ stats,
                             const float* __restrict__ ga, const float* __restrict__ be,
                             const float* __restrict__ clsw, const float* __restrict__ clsb,
                             float* __restrict__ out) {
    int b = blockIdx.x, c = threadIdx.x;  // 128 threads
    float m = stats[2 * c], is = stats[2 * c + 1], gg = ga[c], bb = be[c];
    float s = 0.f;
    for (int n = 0; n < cN; n++) {
        float v = g2[((size_t)(b * cN + n)) * cOUT + c];
        v = (v - m) * is * gg + bb;
        s += fmaxf(v, 0.f);
    }
    __shared__ float feat[cOUT];
    feat[c] = s * (1.f / cN);
    __syncthreads();
    if (c < cNC) {
        float o = clsb[c];
        for (int q = 0; q < cOUT; q++) o += feat[q] * clsw[c * cOUT + q];
        out[b * cNC + c] = o;
    }
}

// ---------------- launch ----------------
extern "C" void kernel_launch(void* const* d_in, const int* in_sizes, int n_in,
                              void* d_out, int out_size) {
    const float* x      = (const float*)d_in[0];
    const float* Wg     = (const float*)d_in[1];
    const float* attn_w = (const float*)d_in[2];
    const float* W1     = (const float*)d_in[3];
    const float* b1     = (const float*)d_in[4];
    const float* w2     = (const float*)d_in[5];
    const float* b2     = (const float*)d_in[6];
    const float* gc1_w  = (const float*)d_in[7];
    const float* gc1_b  = (const float*)d_in[8];
    const float* bn1g   = (const float*)d_in[9];
    const float* bn1b   = (const float*)d_in[10];
    const float* gc2_w  = (const float*)d_in[11];
    const float* gc2_b  = (const float*)d_in[12];
    const float* bn2g   = (const float*)d_in[13];
    const float* bn2b   = (const float*)d_in[14];
    const float* clsw   = (const float*)d_in[15];
    const float* clsb   = (const float*)d_in[16];

    float* buf = nullptr;
    cudaGetSymbolAddress((void**)&buf, g_buf);
    float* hp    = buf + OFF_HP;
    float* alpha = buf + OFF_ALPHA;
    float* nf    = buf + OFF_NF;
    float* pi    = buf + OFF_PI;
    float* pj    = buf + OFF_PJ;
    float* es    = buf + OFF_ES;
    float* sm    = buf + OFF_SM;
    float* adj   = buf + OFF_ADJ;
    float* h1    = buf + OFF_H1;
    float* g1    = buf + OFF_G1;
    float* h2    = buf + OFF_H2;
    float* g2    = buf + OFF_G2;
    float* si    = buf + OFF_SI;
    float* sj    = buf + OFF_SJ;
    float* part  = buf + OFF_PART;
    float* red   = buf + OFF_RED;
    float* bn1s  = buf + OFF_BN1;
    float* bn2s  = buf + OFF_BN2;

    // 1) hp = x @ Wg^T   [1024 x 1024 x 1024]
    gemm_nt<<<dim3(cF / 64, (cB * cN) / 64), 256>>>(x, cF, Wg, cF, hp, cF,
                                                    cB * cN, cF, cF, nullptr);
    // 2) s_i, s_j
    si_sj_kernel<<<cB * cN, 256>>>(hp, attn_w, si, sj);
    // 3) attention softmax -> alpha
    attn_softmax<<<cB * cH * cN, 256>>>(si, sj, alpha);
    // 4) node_feats = alpha @ hp  (batched over b,h; writes into [b,n,h*DH+d])
    gemm_nn<<<dim3(cDH / 64, cN / 64, cB * cH), 256>>>(
        alpha, cN, (long long)cH * NN, (long long)NN,
        hp, cF, (long long)cN * cF, (long long)cDH,
        nf, cF, (long long)cN * cF, (long long)cDH,
        cN, cDH, cN, cH);
    // 5) pi = nf @ W1i^T + b1 ; pj = nf @ W1j^T
    gemm_nt<<<dim3(cAH / 64, (cB * cN) / 64), 256>>>(nf, cF, W1, 2 * cF, pi, cAH,
                                                     cB * cN, cAH, cF, b1);
    gemm_nt<<<dim3(cAH / 64, (cB * cN) / 64), 256>>>(nf, cF, W1 + cF, 2 * cF, pj, cAH,
                                                     cB * cN, cAH, cF, nullptr);
    // 6) edge scores
    edge_kernel<<<dim3(cN / 64, cN / 64, cB), 256>>>(pi, pj, w2, b2, es);
    // 7) flat softmax over N*N (temp 0.5)
    pmax_kernel<<<dim3(128, cB), 256>>>(es, part);
    reduce_part<<<cB, 128>>>(part, red, 0, 0);
    psum_kernel<<<dim3(128, cB), 256>>>(es, red, part);
    reduce_part<<<cB, 128>>>(part, red, 1, 1);
    softmax_write<<<(cB * NN) / 256, 256>>>(es, red, sm);
    // 8) exact order statistic via 4-pass radix select
    sel_init<<<2, 256>>>();
    for (int p = 0; p < 4; p++) {
        sel_hist<<<dim3(64, cB), 256>>>(sm, p);
        sel_step<<<cB, 256>>>(red, p);
    }
    // 9) sum of kept + normalized adjacency
    csum_kernel<<<dim3(128, cB), 256>>>(sm, red, part);
    reduce_part<<<cB, 128>>>(part, red, 1, 3);
    adj_write<<<(cB * NN) / 256, 256>>>(sm, red, adj);
    // 10) h1 = adj @ nf  (batched over b)
    gemm_nn<<<dim3(cF / 64, cN / 64, cB), 256>>>(
        adj, cN, (long long)NN, 0,
        nf, cF, (long long)cN * cF, 0,
        h1, cF, (long long)cN * cF, 0,
        cN, cF, cN, 1);
    // 11) g1 = h1 @ gc1_w^T + gc1_b ; bn1 ; relu
    gemm_nt<<<dim3(cHID / 64, (cB * cN) / 64), 256>>>(h1, cF, gc1_w, cF, g1, cHID,
                                                      cB * cN, cHID, cF, gc1_b);
    bn_stats<<<cHID, 256>>>(g1, cHID, bn1s);
    bn_relu<<<(cB * cN * cHID) / 256, 256>>>(g1, bn1s, bn1g, bn1b, g1, cHID);
    // 12) h2 = adj @ g1
    gemm_nn<<<dim3(cHID / 64, cN / 64, cB), 256>>>(
        adj, cN, (long long)NN, 0,
        g1, cHID, (long long)cN * cHID, 0,
        h2, cHID, (long long)cN * cHID, 0,
        cN, cHID, cN, 1);
    // 13) g2 = h2 @ gc2_w^T + gc2_b ; bn2 stats
    gemm_nt<<<dim3(cOUT / 64, (cB * cN) / 64), 256>>>(h2, cHID, gc2_w, cHID, g2, cOUT,
                                                      cB * cN, cOUT, cHID, gc2_b);
    bn_stats<<<cOUT, 256>>>(g2, cOUT, bn2s);
    // 14) bn2 + relu + mean + classifier
    final_kernel<<<cB, 128>>>(g2, bn2s, bn2g, bn2b, clsw, clsb, (float*)d_out);
}

// round 2
// speedup vs baseline: 1.9959x; 1.9959x over previous
#include <cuda_runtime.h>
#include <math.h>

#define DEV_INLINE __device__ __forceinline__

// ---------------- problem constants ----------------
constexpr int cB = 2, cN = 512, cF = 1024, cH = 4, cDH = 256;
constexpr int cAH = 256, cHID = 512, cOUT = 128, cNC = 10;
constexpr int NN = cN * cN;               // 262144
constexpr int KSEL = 209715;              // int(0.8 * 512 * 512)
constexpr int RANK_SEL = NN - KSEL;       // 52429 : 0-indexed ascending order stat

// ---------------- scratch layout (one big device buffer) ----------------
constexpr size_t OFF_HP    = 0;
constexpr size_t OFF_ALPHA = OFF_HP    + (size_t)cB * cN * cF;
constexpr size_t OFF_NF    = OFF_ALPHA + (size_t)cB * cH * cN * cN;
constexpr size_t OFF_PI    = OFF_NF    + (size_t)cB * cN * cF;
constexpr size_t OFF_PJ    = OFF_PI    + (size_t)cB * cN * cAH;
constexpr size_t OFF_ES    = OFF_PJ    + (size_t)cB * cN * cAH;
constexpr size_t OFF_SM    = OFF_ES    + (size_t)cB * NN;
constexpr size_t OFF_ADJ   = OFF_SM    + (size_t)cB * NN;
constexpr size_t OFF_H1    = OFF_ADJ   + (size_t)cB * NN;
constexpr size_t OFF_G1    = OFF_H1    + (size_t)cB * cN * cF;
constexpr size_t OFF_H2    = OFF_G1    + (size_t)cB * cN * cHID;
constexpr size_t OFF_G2    = OFF_H2    + (size_t)cB * cN * cHID;
constexpr size_t OFF_SI    = OFF_G2    + (size_t)cB * cN * cOUT;
constexpr size_t OFF_SJ    = OFF_SI    + (size_t)cB * cH * cN;
constexpr size_t OFF_PART  = OFF_SJ    + (size_t)cB * cH * cN;
constexpr size_t OFF_RED   = OFF_PART  + (size_t)cB * 128;
constexpr size_t OFF_BN1   = OFF_RED   + (size_t)cB * 8;
constexpr size_t OFF_BN2   = OFF_BN1   + (size_t)2 * cHID;
constexpr size_t BUF_TOTAL = OFF_BN2   + (size_t)2 * cOUT;

__device__ float    g_buf[BUF_TOTAL];
__device__ unsigned g_hist[cB * 256];
__device__ unsigned g_prefix[cB];
__device__ int      g_rank[cB];

// ---------------- reductions ----------------
struct SumOp { DEV_INLINE float operator()(float a, float b) const { return a + b; } };
struct MaxOp { DEV_INLINE float operator()(float a, float b) const { return fmaxf(a, b); } };

template <typename Op>
DEV_INLINE float blockReduceF(float v, Op op, float init) {
    __shared__ float sh[32];
    __syncthreads();
    int lane = threadIdx.x & 31, w = threadIdx.x >> 5;
#pragma unroll
    for (int o = 16; o; o >>= 1) v = op(v, __shfl_down_sync(0xffffffffu, v, o));
    if (lane == 0) sh[w] = v;
    __syncthreads();
    int nw = (blockDim.x + 31) >> 5;
    v = (threadIdx.x < nw) ? sh[threadIdx.x] : init;
    if (w == 0) {
#pragma unroll
        for (int o = 16; o; o >>= 1) v = op(v, __shfl_down_sync(0xffffffffu, v, o));
        if (lane == 0) sh[0] = v;
    }
    __syncthreads();
    return sh[0];
}

DEV_INLINE double blockReduceD(double v) {
    __shared__ double shd[32];
    __syncthreads();
    int lane = threadIdx.x & 31, w = threadIdx.x >> 5;
#pragma unroll
    for (int o = 16; o; o >>= 1) v += __shfl_down_sync(0xffffffffu, v, o);
    if (lane == 0) shd[w] = v;
    __syncthreads();
    int nw = (blockDim.x + 31) >> 5;
    v = (threadIdx.x < nw) ? shd[threadIdx.x] : 0.0;
    if (w == 0) {
#pragma unroll
        for (int o = 16; o; o >>= 1) v += __shfl_down_sync(0xffffffffu, v, o);
        if (lane == 0) shd[0] = v;
    }
    __syncthreads();
    return shd[0];
}

// ---------------- tf32 helpers ----------------
DEV_INLINE unsigned f2tf32(float x) {
    unsigned r;
    asm("cvt.rna.tf32.f32 %0, %1;" : "=r"(r) : "f"(x));
    return r;
}

DEV_INLINE void mma_tf32(float* c, const unsigned* a, unsigned b0, unsigned b1) {
    asm volatile(
        "mma.sync.aligned.m16n8k8.row.col.f32.tf32.tf32.f32 "
        "{%0,%1,%2,%3}, {%4,%5,%6,%7}, {%8,%9}, {%0,%1,%2,%3};\n"
        : "+f"(c[0]), "+f"(c[1]), "+f"(c[2]), "+f"(c[3])
        : "r"(a[0]), "r"(a[1]), "r"(a[2]), "r"(a[3]), "r"(b0), "r"(b1));
}

// ---------------- unified tensor-core GEMM (3xTF32 split, fp32-accurate) ----
// C[m,n] = sum_k A[m,k] * B'[k,n]  where B' = B[n,k] if b_nk else B[k,n].
// 64x64 tile, ktile 16, 128 threads (4 warps, 2x2), warp tile 32x32.
// Batched via blockIdx.z -> (z1 = z/HH, z2 = z%HH), per-operand strides.
// Bias added per output column when bias != null and z2 < bias_z.
constexpr int SMP = 68;

__global__ __launch_bounds__(128) void gemm_tc(
    const float* __restrict__ A, int lda, long long sA1, long long sA2,
    const float* __restrict__ B, int ldb, long long sB1, long long sB2,
    float* __restrict__ C, int ldc, long long sC1, long long sC2,
    int M, int Nd, int K, int HH,
    const float* __restrict__ bias, int bias_z, int b_nk) {
    __shared__ unsigned As_h[16][SMP], As_l[16][SMP];
    __shared__ unsigned Bs_h[16][SMP], Bs_l[16][SMP];
    int z = blockIdx.z, z1 = z / HH, z2 = z % HH;
    A += (size_t)z1 * sA1 + (size_t)z2 * sA2;
    B += (size_t)z1 * sB1 + (size_t)z2 * sB2;
    C += (size_t)z1 * sC1 + (size_t)z2 * sC2;
    int tid = threadIdx.x;
    int m0 = blockIdx.y * 64, n0 = blockIdx.x * 64;
    int lane = tid & 31, wid = tid >> 5;
    int wm = (wid >> 1) * 32, wn = (wid & 1) * 32;
    int tg = lane & 3, gp = lane >> 2;
    float acc[2][4][4] = {};
    const float* Ag = A + (size_t)m0 * lda;
    const float* Bg_nt = B + (size_t)n0 * ldb;

    for (int k0 = 0; k0 < K; k0 += 16) {
        // load A tile [64 rows m x 16 k] -> As[k][m] (hi/lo split)
#pragma unroll
        for (int it = 0; it < 2; it++) {
            int idx = tid + it * 128;
            int r = idx >> 2, kc = (idx & 3) * 4;
            float4 v = *reinterpret_cast<const float4*>(Ag + (size_t)r * lda + k0 + kc);
            float f[4] = {v.x, v.y, v.z, v.w};
#pragma unroll
            for (int j = 0; j < 4; j++) {
                unsigned hi = f2tf32(f[j]);
                As_h[kc + j][r] = hi;
                As_l[kc + j][r] = f2tf32(f[j] - __uint_as_float(hi));
            }
        }
        // load B tile -> Bs[k][n]
        if (b_nk) {
#pragma unroll
            for (int it = 0; it < 2; it++) {
                int idx = tid + it * 128;
                int r = idx >> 2, kc = (idx & 3) * 4;
                float4 v = *reinterpret_cast<const float4*>(Bg_nt + (size_t)r * ldb + k0 + kc);
                float f[4] = {v.x, v.y, v.z, v.w};
#pragma unroll
                for (int j = 0; j < 4; j++) {
                    unsigned hi = f2tf32(f[j]);
                    Bs_h[kc + j][r] = hi;
                    Bs_l[kc + j][r] = f2tf32(f[j] - __uint_as_float(hi));
                }
            }
        } else {
#pragma unroll
            for (int it = 0; it < 2; it++) {
                int idx = tid + it * 128;
                int kr = idx >> 4, nc = (idx & 15) * 4;
                float4 v = *reinterpret_cast<const float4*>(B + (size_t)(k0 + kr) * ldb + n0 + nc);
                float f[4] = {v.x, v.y, v.z, v.w};
#pragma unroll
                for (int j = 0; j < 4; j++) {
                    unsigned hi = f2tf32(f[j]);
                    Bs_h[kr][nc + j] = hi;
                    Bs_l[kr][nc + j] = f2tf32(f[j] - __uint_as_float(hi));
                }
            }
        }
        __syncthreads();
#pragma unroll
        for (int kk = 0; kk < 16; kk += 8) {
            unsigned ah[2][4], al[2][4];
#pragma unroll
            for (int mt = 0; mt < 2; mt++) {
                int m = wm + mt * 16 + gp;
                ah[mt][0] = As_h[kk + tg][m];     ah[mt][1] = As_h[kk + tg][m + 8];
                ah[mt][2] = As_h[kk + tg + 4][m]; ah[mt][3] = As_h[kk + tg + 4][m + 8];
                al[mt][0] = As_l[kk + tg][m];     al[mt][1] = As_l[kk + tg][m + 8];
                al[mt][2] = As_l[kk + tg + 4][m]; al[mt][3] = As_l[kk + tg + 4][m + 8];
            }
#pragma unroll
            for (int nt = 0; nt < 4; nt++) {
                int n = wn + nt * 8 + gp;
                unsigned bh0 = Bs_h[kk + tg][n], bh1 = Bs_h[kk + tg + 4][n];
                unsigned bl0 = Bs_l[kk + tg][n], bl1 = Bs_l[kk + tg + 4][n];
#pragma unroll
                for (int mt = 0; mt < 2; mt++) {
                    mma_tf32(acc[mt][nt], ah[mt], bh0, bh1);
                    mma_tf32(acc[mt][nt], al[mt], bh0, bh1);
                    mma_tf32(acc[mt][nt], ah[mt], bl0, bl1);
                }
            }
        }
        __syncthreads();
    }
    // epilogue
    bool useb = (bias != nullptr) && (z2 < bias_z);
#pragma unroll
    for (int mt = 0; mt < 2; mt++) {
        int r = m0 + wm + mt * 16 + gp;
#pragma unroll
        for (int nt = 0; nt < 4; nt++) {
            int ncol = n0 + wn + nt * 8 + tg * 2;
            float b0v = useb ? bias[ncol] : 0.f;
            float b1v = useb ? bias[ncol + 1] : 0.f;
            C[(size_t)r * ldc + ncol]           = acc[mt][nt][0] + b0v;
            C[(size_t)r * ldc + ncol + 1]       = acc[mt][nt][1] + b1v;
            C[(size_t)(r + 8) * ldc + ncol]     = acc[mt][nt][2] + b0v;
            C[(size_t)(r + 8) * ldc + ncol + 1] = acc[mt][nt][3] + b1v;
        }
    }
}

// ---------------- attention scores s_i, s_j ----------------
__global__ void si_sj_kernel(const float* __restrict__ hp, const float* __restrict__ attn_w,
                             float* __restrict__ si, float* __restrict__ sj) {
    int bn = blockIdx.x;
    int b = bn >> 9, n = bn & 511;
    const float* row = hp + (size_t)bn * cF;
    int t = threadIdx.x;  // 256
    for (int h = 0; h < cH; h++) {
        float v = row[h * cDH + t];
        float vi = v * attn_w[h * 2 * cDH + t];
        float vj = v * attn_w[h * 2 * cDH + cDH + t];
        float s1 = blockReduceF(vi, SumOp(), 0.f);
        float s2 = blockReduceF(vj, SumOp(), 0.f);
        if (t == 0) {
            si[((size_t)b * cH + h) * cN + n] = s1;
            sj[((size_t)b * cH + h) * cN + n] = s2;
        }
    }
}

// ---------------- per-row attention softmax (leakyrelu(si+sj)) ----------------
__global__ void attn_softmax(const float* __restrict__ si, const float* __restrict__ sj,
                             float* __restrict__ alpha) {
    int id = blockIdx.x;          // bh*cN + i
    int i = id & 511, bh = id >> 9;
    float s_i = si[(size_t)bh * cN + i];
    const float* sjr = sj + (size_t)bh * cN;
    int t = threadIdx.x;  // 256, 2 j per thread
    float x0 = s_i + sjr[t];
    float x1 = s_i + sjr[t + 256];
    float e0 = x0 >= 0.f ? x0 : 0.2f * x0;
    float e1 = x1 >= 0.f ? x1 : 0.2f * x1;
    float m = blockReduceF(fmaxf(e0, e1), MaxOp(), -1e30f);
    float p0 = expf(e0 - m), p1 = expf(e1 - m);
    float s = blockReduceF(p0 + p1, SumOp(), 0.f);
    float inv = 1.f / s;
    float* arow = alpha + (size_t)id * cN;
    arow[t] = p0 * inv;
    arow[t + 256] = p1 * inv;
}

// ---------------- edge MLP: es[b,i,j] = sum_a relu(pi'+pj)*w2 + b2 ----------------
__global__ void edge_kernel(const float* __restrict__ pi, const float* __restrict__ pj,
                            const float* __restrict__ w2, const float* __restrict__ b2,
                            float* __restrict__ es) {
    __shared__ float pis[32][65];
    __shared__ float pjs[32][65];
    __shared__ float w2s[32];
    int b = blockIdx.z;
    int i0 = blockIdx.y * 64, j0 = blockIdx.x * 64;
    int tid = threadIdx.x;
    int tx = tid & 15, ty = tid >> 4;
    float acc[4][4] = {};
    for (int a0 = 0; a0 < cAH; a0 += 32) {
        for (int idx = tid; idx < 64 * 32; idx += 256) {
            int a = idx & 31, r = idx >> 5;
            pis[a][r] = pi[((size_t)(b * cN + i0 + r)) * cAH + a0 + a];
            pjs[a][r] = pj[((size_t)(b * cN + j0 + r)) * cAH + a0 + a];
        }
        if (tid < 32) w2s[tid] = w2[a0 + tid];
        __syncthreads();
#pragma unroll 8
        for (int a = 0; a < 32; a++) {
            float w = w2s[a];
            float pv[4], qv[4];
#pragma unroll
            for (int u = 0; u < 4; u++) pv[u] = pis[a][ty + 16 * u];
#pragma unroll
            for (int v = 0; v < 4; v++) qv[v] = pjs[a][tx + 16 * v];
#pragma unroll
            for (int u = 0; u < 4; u++)
#pragma unroll
                for (int v = 0; v < 4; v++)
                    acc[u][v] += fmaxf(pv[u] + qv[v], 0.f) * w;
        }
        __syncthreads();
    }
    float bb = b2[0];
#pragma unroll
    for (int u = 0; u < 4; u++)
#pragma unroll
        for (int v = 0; v < 4; v++)
            es[((size_t)b * cN + i0 + ty + 16 * u) * cN + j0 + tx + 16 * v] = acc[u][v] + bb;
}

// ---------------- flat softmax (scale 1/TEMP = 2) ----------------
__global__ void pmax_kernel(const float* __restrict__ es, float* __restrict__ part) {
    int b = blockIdx.y, seg = blockIdx.x;  // 128 segs of 2048
    const float* p = es + (size_t)b * NN + seg * 2048;
    float m = -1e30f;
    for (int i = threadIdx.x; i < 2048; i += 256) m = fmaxf(m, p[i]);
    m = blockReduceF(m, MaxOp(), -1e30f);
    if (threadIdx.x == 0) part[b * 128 + seg] = m;
}

__global__ void psum_kernel(const float* __restrict__ es, const float* __restrict__ red,
                            float* __restrict__ part) {
    int b = blockIdx.y, seg = blockIdx.x;
    float m = red[b * 8 + 0];
    const float* p = es + (size_t)b * NN + seg * 2048;
    float s = 0.f;
    for (int i = threadIdx.x; i < 2048; i += 256) s += expf(2.f * (p[i] - m));
    s = blockReduceF(s, SumOp(), 0.f);
    if (threadIdx.x == 0) part[b * 128 + seg] = s;
}

__global__ void reduce_part(const float* __restrict__ part, float* __restrict__ red,
                            int mode /*0 max,1 sum*/, int slot) {
    int b = blockIdx.x;
    float v = part[b * 128 + threadIdx.x];  // 128 threads
    v = mode ? blockReduceF(v, SumOp(), 0.f) : blockReduceF(v, MaxOp(), -1e30f);
    if (threadIdx.x == 0) red[b * 8 + slot] = v;
}

__global__ void softmax_write(const float* __restrict__ es, const float* __restrict__ red,
                              float* __restrict__ sm) {
    size_t i = (size_t)blockIdx.x * blockDim.x + threadIdx.x;
    int b = (int)(i / NN);
    float m = red[b * 8 + 0];
    float inv = 1.f / red[b * 8 + 1];
    sm[i] = expf(2.f * (es[i] - m)) * inv;
}

// ---------------- exact radix select (positive floats, MSB-first) ----------------
__global__ void sel_init() {
    int t = blockIdx.x * blockDim.x + threadIdx.x;
    if (t < cB * 256) g_hist[t] = 0;
    if (t < cB) { g_prefix[t] = 0; g_rank[t] = RANK_SEL; }
}

__global__ void sel_hist(const float* __restrict__ sm, int pass) {
    int b = blockIdx.y;
    int shift = 24 - 8 * pass;
    unsigned prefix = g_prefix[b];
    __shared__ unsigned hist[256];
    hist[threadIdx.x] = 0;
    __syncthreads();
    const unsigned* data = reinterpret_cast<const unsigned*>(sm) + (size_t)b * NN;
    int per = NN / gridDim.x;
    int base = blockIdx.x * per;
    for (int i = threadIdx.x; i < per; i += 256) {
        unsigned u = data[base + i];
        bool ok = (pass == 0) || ((u >> (shift + 8)) == (prefix >> (shift + 8)));
        int bin = ok ? (int)((u >> shift) & 255u) : -1;
        unsigned mask = __match_any_sync(0xffffffffu, bin);
        if (bin >= 0 && ((threadIdx.x & 31) == (__ffs(mask) - 1)))
            atomicAdd(&hist[bin], (unsigned)__popc(mask));
    }
    __syncthreads();
    if (hist[threadIdx.x]) atomicAdd(&g_hist[b * 256 + threadIdx.x], hist[threadIdx.x]);
}

__global__ void sel_step(float* __restrict__ red, int pass) {
    int b = blockIdx.x;
    int shift = 24 - 8 * pass;
    if (threadIdx.x == 0) {
        int r = g_rank[b];
        unsigned cum = 0;
        int sel = 0;
        for (int x = 0; x < 256; x++) {
            unsigned h = g_hist[b * 256 + x];
            if (cum + h > (unsigned)r) { sel = x; break; }
            cum += h;
        }
        g_rank[b] = r - (int)cum;
        unsigned p = g_prefix[b] | ((unsigned)sel << shift);
        g_prefix[b] = p;
        if (pass == 3) red[b * 8 + 2] = __uint_as_float(p);
    }
    __syncthreads();
    g_hist[b * 256 + threadIdx.x] = 0;  // reset for next pass
}

__global__ void csum_kernel(const float* __restrict__ sm, const float* __restrict__ red,
                            float* __restrict__ part) {
    int b = blockIdx.y, seg = blockIdx.x;
    float thr = red[b * 8 + 2];
    const float* p = sm + (size_t)b * NN + seg * 2048;
    float s = 0.f;
    for (int i = threadIdx.x; i < 2048; i += 256) {
        float v = p[i];
        if (v >= thr) s += v;
    }
    s = blockReduceF(s, SumOp(), 0.f);
    if (threadIdx.x == 0) part[b * 128 + seg] = s;
}

__global__ void adj_write(const float* __restrict__ sm, const float* __restrict__ red,
                          float* __restrict__ adj) {
    size_t i = (size_t)blockIdx.x * blockDim.x + threadIdx.x;
    int b = (int)(i / NN);
    float thr = red[b * 8 + 2];
    float inv = 1.f / (red[b * 8 + 3] + 1e-12f);
    float v = sm[i];
    adj[i] = (v >= thr) ? v * inv : 0.f;
}

// ---------------- batchnorm ----------------
__global__ void bn_stats(const float* __restrict__ h, int C, float* __restrict__ stats) {
    int c = blockIdx.x;
    double s = 0.0, s2 = 0.0;
    for (int r = threadIdx.x; r < cB * cN; r += blockDim.x) {
        double v = (double)h[(size_t)r * C + c];
        s += v;
        s2 += v * v;
    }
    s = blockReduceD(s);
    s2 = blockReduceD(s2);
    if (threadIdx.x == 0) {
        double m = s / (cB * cN);
        double var = s2 / (cB * cN) - m * m;
        stats[2 * c] = (float)m;
        stats[2 * c + 1] = (float)rsqrt(var + 1e-5);
    }
}

__global__ void bn_relu(const float* __restrict__ h, const float* __restrict__ stats,
                        const float* __restrict__ gamma, const float* __restrict__ beta,
                        float* __restrict__ out, int C) {
    size_t i = (size_t)blockIdx.x * blockDim.x + threadIdx.x;
    int c = (int)(i % C);
    float v = (h[i] - stats[2 * c]) * stats[2 * c + 1] * gamma[c] + beta[c];
    out[i] = fmaxf(v, 0.f);
}

// ---------------- final: bn2 + relu + mean over N + classifier ----------------
__global__ void final_kernel(const float* __restrict__ g2, const float* __restrict__ stats,
                             const float* __restrict__ ga, const float* __restrict__ be,
                             const float* __restrict__ clsw, const float* __restrict__ clsb,
                             float* __restrict__ out) {
    int b = blockIdx.x, c = threadIdx.x;  // 128 threads
    float m = stats[2 * c], is = stats[2 * c + 1], gg = ga[c], bb = be[c];
    float s = 0.f;
    for (int n = 0; n < cN; n++) {
        float v = g2[((size_t)(b * cN + n)) * cOUT + c];
        v = (v - m) * is * gg + bb;
        s += fmaxf(v, 0.f);
    }
    __shared__ float feat[cOUT];
    feat[c] = s * (1.f / cN);
    __syncthreads();
    if (c < cNC) {
        float o = clsb[c];
        for (int q = 0; q < cOUT; q++) o += feat[q] * clsw[c * cOUT + q];
        out[b * cNC + c] = o;
    }
}

// ---------------- launch ----------------
extern "C" void kernel_launch(void* const* d_in, const int* in_sizes, int n_in,
                              void* d_out, int out_size) {
    const float* x      = (const float*)d_in[0];
    const float* Wg     = (const float*)d_in[1];
    const float* attn_w = (const float*)d_in[2];
    const float* W1     = (const float*)d_in[3];
    const float* b1     = (const float*)d_in[4];
    const float* w2     = (const float*)d_in[5];
    const float* b2     = (const float*)d_in[6];
    const float* gc1_w  = (const float*)d_in[7];
    const float* gc1_b  = (const float*)d_in[8];
    const float* bn1g   = (const float*)d_in[9];
    const float* bn1b   = (const float*)d_in[10];
    const float* gc2_w  = (const float*)d_in[11];
    const float* gc2_b  = (const float*)d_in[12];
    const float* bn2g   = (const float*)d_in[13];
    const float* bn2b   = (const float*)d_in[14];
    const float* clsw   = (const float*)d_in[15];
    const float* clsb   = (const float*)d_in[16];

    float* buf = nullptr;
    cudaGetSymbolAddress((void**)&buf, g_buf);
    float* hp    = buf + OFF_HP;
    float* alpha = buf + OFF_ALPHA;
    float* nf    = buf + OFF_NF;
    float* pi    = buf + OFF_PI;
    float* es    = buf + OFF_ES;
    float* sm    = buf + OFF_SM;
    float* adj   = buf + OFF_ADJ;
    float* h1    = buf + OFF_H1;
    float* g1    = buf + OFF_G1;
    float* h2    = buf + OFF_H2;
    float* g2    = buf + OFF_G2;
    float* si    = buf + OFF_SI;
    float* sj    = buf + OFF_SJ;
    float* part  = buf + OFF_PART;
    float* red   = buf + OFF_RED;
    float* bn1s  = buf + OFF_BN1;
    float* bn2s  = buf + OFF_BN2;
    float* pj    = buf + OFF_PJ;

    typedef long long ll;

    // 1) hp = x @ Wg^T   [1024 x 1024 x 1024]
    gemm_tc<<<dim3(cF / 64, (cB * cN) / 64, 1), 128>>>(
        x, cF, 0, 0, Wg, cF, 0, 0, hp, cF, 0, 0,
        cB * cN, cF, cF, 1, nullptr, 0, 1);
    // 2) s_i, s_j
    si_sj_kernel<<<cB * cN, 256>>>(hp, attn_w, si, sj);
    // 3) attention softmax -> alpha
    attn_softmax<<<cB * cH * cN, 256>>>(si, sj, alpha);
    // 4) node_feats = alpha @ hp  (batched over b,h)
    gemm_tc<<<dim3(cDH / 64, cN / 64, cB * cH), 128>>>(
        alpha, cN, (ll)cH * NN, (ll)NN,
        hp, cF, (ll)cN * cF, (ll)cDH,
        nf, cF, (ll)cN * cF, (ll)cDH,
        cN, cDH, cN, cH, nullptr, 0, 0);
    // 5) pi = nf @ W1i^T + b1 ; pj = nf @ W1j^T  (fused: grid.z = 2)
    gemm_tc<<<dim3(cAH / 64, (cB * cN) / 64, 2), 128>>>(
        nf, cF, 0, 0,
        W1, 2 * cF, 0, (ll)cF,
        pi, cAH, 0, (ll)cB * cN * cAH,
        cB * cN, cAH, cF, 2, b1, 1, 1);
    // 6) edge scores
    edge_kernel<<<dim3(cN / 64, cN / 64, cB), 256>>>(pi, pj, w2, b2, es);
    // 7) flat softmax over N*N (temp 0.5)
    pmax_kernel<<<dim3(128, cB), 256>>>(es, part);
    reduce_part<<<cB, 128>>>(part, red, 0, 0);
    psum_kernel<<<dim3(128, cB), 256>>>(es, red, part);
    reduce_part<<<cB, 128>>>(part, red, 1, 1);
    softmax_write<<<(cB * NN) / 256, 256>>>(es, red, sm);
    // 8) exact order statistic via 4-pass radix select
    sel_init<<<2, 256>>>();
    for (int p = 0; p < 4; p++) {
        sel_hist<<<dim3(64, cB), 256>>>(sm, p);
        sel_step<<<cB, 256>>>(red, p);
    }
    // 9) sum of kept + normalized adjacency
    csum_kernel<<<dim3(128, cB), 256>>>(sm, red, part);
    reduce_part<<<cB, 128>>>(part, red, 1, 3);
    adj_write<<<(cB * NN) / 256, 256>>>(sm, red, adj);
    // 10) h1 = adj @ nf  (batched over b)
    gemm_tc<<<dim3(cF / 64, cN / 64, cB), 128>>>(
        adj, cN, (ll)NN, 0,
        nf, cF, (ll)cN * cF, 0,
        h1, cF, (ll)cN * cF, 0,
        cN, cF, cN, 1, nullptr, 0, 0);
    // 11) g1 = h1 @ gc1_w^T + gc1_b ; bn1 ; relu
    gemm_tc<<<dim3(cHID / 64, (cB * cN) / 64, 1), 128>>>(
        h1, cF, 0, 0, gc1_w, cF, 0, 0, g1, cHID, 0, 0,
        cB * cN, cHID, cF, 1, gc1_b, 1, 1);
    bn_stats<<<cHID, 256>>>(g1, cHID, bn1s);
    bn_relu<<<(cB * cN * cHID) / 256, 256>>>(g1, bn1s, bn1g, bn1b, g1, cHID);
    // 12) h2 = adj @ g1
    gemm_tc<<<dim3(cHID / 64, cN / 64, cB), 128>>>(
        adj, cN, (ll)NN, 0,
        g1, cHID, (ll)cN * cHID, 0,
        h2, cHID, (ll)cN * cHID, 0,
        cN, cHID, cN, 1, nullptr, 0, 0);
    // 13) g2 = h2 @ gc2_w^T + gc2_b ; bn2 stats
    gemm_tc<<<dim3(cOUT / 64, (cB * cN) / 64, 1), 128>>>(
        h2, cHID, 0, 0, gc2_w, cHID, 0, 0, g2, cOUT, 0, 0,
        cB * cN, cOUT, cHID, 1, gc2_b, 1, 1);
    bn_stats<<<cOUT, 256>>>(g2, cOUT, bn2s);
    // 14) bn2 + relu + mean + classifier
    final_kernel<<<cB, 128>>>(g2, bn2s, bn2g, bn2b, clsw, clsb, (float*)d_out);
}

// round 3
// speedup vs baseline: 3.3955x; 1.7013x over previous
#include <cuda_runtime.h>
#include <math.h>

#define DEV_INLINE __device__ __forceinline__

// ---------------- problem constants ----------------
constexpr int cB = 2, cN = 512, cF = 1024, cH = 4, cDH = 256;
constexpr int cAH = 256, cHID = 512, cOUT = 128, cNC = 10;
constexpr int NN = cN * cN;               // 262144
constexpr int KSEL = 209715;              // int(0.8 * 512 * 512)
constexpr int RANK_SEL = NN - KSEL;       // 52429

// ---------------- scratch layout ----------------
constexpr size_t OFF_HP    = 0;
constexpr size_t OFF_ALPHA = OFF_HP    + (size_t)cB * cN * cF;
constexpr size_t OFF_NF    = OFF_ALPHA + (size_t)cB * cH * cN * cN;
constexpr size_t OFF_PI    = OFF_NF    + (size_t)cB * cN * cF;
constexpr size_t OFF_PJ    = OFF_PI    + (size_t)cB * cN * cAH;
constexpr size_t OFF_ES    = OFF_PJ    + (size_t)cB * cN * cAH;
constexpr size_t OFF_SM    = OFF_ES    + (size_t)cB * NN;
constexpr size_t OFF_ADJ   = OFF_SM    + (size_t)cB * NN;
constexpr size_t OFF_H1    = OFF_ADJ   + (size_t)cB * NN;
constexpr size_t OFF_G1    = OFF_H1    + (size_t)cB * cN * cF;
constexpr size_t OFF_H2    = OFF_G1    + (size_t)cB * cN * cHID;
constexpr size_t OFF_G2    = OFF_H2    + (size_t)cB * cN * cHID;
constexpr size_t OFF_SI    = OFF_G2    + (size_t)cB * cN * cOUT;
constexpr size_t OFF_SJ    = OFF_SI    + (size_t)cB * cH * cN;
constexpr size_t OFF_PART  = OFF_SJ    + (size_t)cB * cH * cN;
constexpr size_t OFF_RED   = OFF_PART  + (size_t)cB * 128;
constexpr size_t OFF_BN1   = OFF_RED   + (size_t)cB * 8;
constexpr size_t OFF_BN2   = OFF_BN1   + (size_t)2 * cHID;
constexpr size_t BUF_TOTAL = OFF_BN2   + (size_t)2 * cOUT;

__device__ float    g_buf[BUF_TOTAL];
__device__ unsigned g_hist[cB * 256];
__device__ unsigned g_prefix[cB];
__device__ int      g_rank[cB];

// ---------------- reductions ----------------
struct SumOp { DEV_INLINE float operator()(float a, float b) const { return a + b; } };
struct MaxOp { DEV_INLINE float operator()(float a, float b) const { return fmaxf(a, b); } };

template <typename Op>
DEV_INLINE float blockReduceF(float v, Op op, float init) {
    __shared__ float sh[32];
    __syncthreads();
    int lane = threadIdx.x & 31, w = threadIdx.x >> 5;
#pragma unroll
    for (int o = 16; o; o >>= 1) v = op(v, __shfl_down_sync(0xffffffffu, v, o));
    if (lane == 0) sh[w] = v;
    __syncthreads();
    int nw = (blockDim.x + 31) >> 5;
    v = (threadIdx.x < nw) ? sh[threadIdx.x] : init;
    if (w == 0) {
#pragma unroll
        for (int o = 16; o; o >>= 1) v = op(v, __shfl_down_sync(0xffffffffu, v, o));
        if (lane == 0) sh[0] = v;
    }
    __syncthreads();
    return sh[0];
}

DEV_INLINE double blockReduceD(double v) {
    __shared__ double shd[32];
    __syncthreads();
    int lane = threadIdx.x & 31, w = threadIdx.x >> 5;
#pragma unroll
    for (int o = 16; o; o >>= 1) v += __shfl_down_sync(0xffffffffu, v, o);
    if (lane == 0) shd[w] = v;
    __syncthreads();
    int nw = (blockDim.x + 31) >> 5;
    v = (threadIdx.x < nw) ? shd[threadIdx.x] : 0.0;
    if (w == 0) {
#pragma unroll
        for (int o = 16; o; o >>= 1) v += __shfl_down_sync(0xffffffffu, v, o);
        if (lane == 0) shd[0] = v;
    }
    __syncthreads();
    return shd[0];
}

// ---------------- bf16 split helpers ----------------
// pair = {low16 = bf16(f_even), high16 = bf16(f_odd)}
DEV_INLINE unsigned pack_bf2(float f_even, float f_odd) {
    unsigned r;
    asm("cvt.rn.bf16x2.f32 %0, %1, %2;" : "=r"(r) : "f"(f_odd), "f"(f_even));
    return r;
}
// split 2 floats into hi pair + lo pair
DEV_INLINE void split2(float f0, float f1, unsigned& hi, unsigned& lo) {
    hi = pack_bf2(f0, f1);
    float h0 = __uint_as_float(hi << 16);
    float h1 = __uint_as_float(hi & 0xFFFF0000u);
    lo = pack_bf2(f0 - h0, f1 - h1);
}

DEV_INLINE void mma_bf16(float* c, const unsigned* a, unsigned b0, unsigned b1) {
    asm volatile(
        "mma.sync.aligned.m16n8k16.row.col.f32.bf16.bf16.f32 "
        "{%0,%1,%2,%3}, {%4,%5,%6,%7}, {%8,%9}, {%0,%1,%2,%3};\n"
        : "+f"(c[0]), "+f"(c[1]), "+f"(c[2]), "+f"(c[3])
        : "r"(a[0]), "r"(a[1]), "r"(a[2]), "r"(a[3]), "r"(b0), "r"(b1));
}

// ---------------- tensor-core GEMM (3xBF16 split, near-fp32 accuracy) -------
// C[m,n] = sum_k A[m,k] * B'[k,n]  where B' = B[n,k] if b_nk else B[k,n].
// 64x64 tile, ktile 32 (16 bf16x2 k-pairs), 128 threads (4 warps, 2x2).
// smem: [kp][m] packed bf16x2 pairs; register-prefetch pipeline.
constexpr int SMP = 68;

__global__ __launch_bounds__(128) void gemm_tc(
    const float* __restrict__ A, int lda, long long sA1, long long sA2,
    const float* __restrict__ B, int ldb, long long sB1, long long sB2,
    float* __restrict__ C, int ldc, long long sC1, long long sC2,
    int M, int Nd, int K, int HH,
    const float* __restrict__ bias, int bias_z, int b_nk) {
    __shared__ unsigned As_h[16][SMP], As_l[16][SMP];
    __shared__ unsigned Bs_h[16][SMP], Bs_l[16][SMP];
    int z = blockIdx.z, z1 = z / HH, z2 = z % HH;
    A += (size_t)z1 * sA1 + (size_t)z2 * sA2;
    B += (size_t)z1 * sB1 + (size_t)z2 * sB2;
    C += (size_t)z1 * sC1 + (size_t)z2 * sC2;
    int tid = threadIdx.x;
    int m0 = blockIdx.y * 64, n0 = blockIdx.x * 64;
    int lane = tid & 31, wid = tid >> 5;
    int wm = (wid >> 1) * 32, wn = (wid & 1) * 32;
    int tg = lane & 3, gp = lane >> 2;
    float acc[2][4][4] = {};
    const float* Ag = A + (size_t)m0 * lda;
    const float* Bg_nt = B + (size_t)n0 * ldb;

    float4 pa[4], pb[4];

    // prefetch helpers (A: 64 rows x 32 k -> 512 float4, 4/thread)
    auto loadA = [&](int k0) {
#pragma unroll
        for (int it = 0; it < 4; it++) {
            int idx = tid + it * 128;
            int r = idx >> 3, c4 = idx & 7;
            pa[it] = *reinterpret_cast<const float4*>(Ag + (size_t)r * lda + k0 + c4 * 4);
        }
    };
    auto storeA = [&]() {
#pragma unroll
        for (int it = 0; it < 4; it++) {
            int idx = tid + it * 128;
            int r = idx >> 3, kp = (idx & 7) * 2;
            unsigned h0, l0, h1, l1;
            split2(pa[it].x, pa[it].y, h0, l0);
            split2(pa[it].z, pa[it].w, h1, l1);
            As_h[kp][r] = h0;     As_l[kp][r] = l0;
            As_h[kp + 1][r] = h1; As_l[kp + 1][r] = l1;
        }
    };
    auto loadB = [&](int k0) {
        if (b_nk) {
#pragma unroll
            for (int it = 0; it < 4; it++) {
                int idx = tid + it * 128;
                int r = idx >> 3, c4 = idx & 7;
                pb[it] = *reinterpret_cast<const float4*>(Bg_nt + (size_t)r * ldb + k0 + c4 * 4);
            }
        } else {
            // [k][n]: 16 kp-rows x 16 n-chunks; thread covers 2 (kp,nc) items, 2 rows each
#pragma unroll
            for (int it = 0; it < 2; it++) {
                int idx = tid + it * 128;
                int kp = idx >> 4, nc = (idx & 15) * 4;
                pb[it * 2]     = *reinterpret_cast<const float4*>(B + (size_t)(k0 + 2 * kp) * ldb + n0 + nc);
                pb[it * 2 + 1] = *reinterpret_cast<const float4*>(B + (size_t)(k0 + 2 * kp + 1) * ldb + n0 + nc);
            }
        }
    };
    auto storeB = [&]() {
        if (b_nk) {
#pragma unroll
            for (int it = 0; it < 4; it++) {
                int idx = tid + it * 128;
                int r = idx >> 3, kp = (idx & 7) * 2;
                unsigned h0, l0, h1, l1;
                split2(pb[it].x, pb[it].y, h0, l0);
                split2(pb[it].z, pb[it].w, h1, l1);
                Bs_h[kp][r] = h0;     Bs_l[kp][r] = l0;
                Bs_h[kp + 1][r] = h1; Bs_l[kp + 1][r] = l1;
            }
        } else {
#pragma unroll
            for (int it = 0; it < 2; it++) {
                int idx = tid + it * 128;
                int kp = idx >> 4, nc = (idx & 15) * 4;
                float4 e = pb[it * 2], o = pb[it * 2 + 1];
                float fe[4] = {e.x, e.y, e.z, e.w};
                float fo[4] = {o.x, o.y, o.z, o.w};
#pragma unroll
                for (int j = 0; j < 4; j++) {
                    unsigned h, l;
                    split2(fe[j], fo[j], h, l);  // pair along k: (even row, odd row)
                    Bs_h[kp][nc + j] = h;
                    Bs_l[kp][nc + j] = l;
                }
            }
        }
    };

    loadA(0);
    loadB(0);
    for (int k0 = 0; k0 < K; k0 += 32) {
        storeA();
        storeB();
        __syncthreads();
        if (k0 + 32 < K) { loadA(k0 + 32); loadB(k0 + 32); }
#pragma unroll
        for (int ks = 0; ks < 16; ks += 8) {  // two k16 steps (8 kp each)
            unsigned ah[2][4], al[2][4];
#pragma unroll
            for (int mt = 0; mt < 2; mt++) {
                int m = wm + mt * 16 + gp;
                ah[mt][0] = As_h[ks + tg][m];     ah[mt][1] = As_h[ks + tg][m + 8];
                ah[mt][2] = As_h[ks + tg + 4][m]; ah[mt][3] = As_h[ks + tg + 4][m + 8];
                al[mt][0] = As_l[ks + tg][m];     al[mt][1] = As_l[ks + tg][m + 8];
                al[mt][2] = As_l[ks + tg + 4][m]; al[mt][3] = As_l[ks + tg + 4][m + 8];
            }
            unsigned bh0[4], bh1[4], bl0[4], bl1[4];
#pragma unroll
            for (int nt = 0; nt < 4; nt++) {
                int n = wn + nt * 8 + gp;
                bh0[nt] = Bs_h[ks + tg][n]; bh1[nt] = Bs_h[ks + tg + 4][n];
                bl0[nt] = Bs_l[ks + tg][n]; bl1[nt] = Bs_l[ks + tg + 4][n];
            }
            // three passes: hi*hi, lo*hi, hi*lo — 8 independent acc chains per pass
#pragma unroll
            for (int nt = 0; nt < 4; nt++)
#pragma unroll
                for (int mt = 0; mt < 2; mt++)
                    mma_bf16(acc[mt][nt], ah[mt], bh0[nt], bh1[nt]);
#pragma unroll
            for (int nt = 0; nt < 4; nt++)
#pragma unroll
                for (int mt = 0; mt < 2; mt++)
                    mma_bf16(acc[mt][nt], al[mt], bh0[nt], bh1[nt]);
#pragma unroll
            for (int nt = 0; nt < 4; nt++)
#pragma unroll
                for (int mt = 0; mt < 2; mt++)
                    mma_bf16(acc[mt][nt], ah[mt], bl0[nt], bl1[nt]);
        }
        __syncthreads();
    }
    // epilogue
    bool useb = (bias != nullptr) && (z2 < bias_z);
#pragma unroll
    for (int mt = 0; mt < 2; mt++) {
        int r = m0 + wm + mt * 16 + gp;
#pragma unroll
        for (int nt = 0; nt < 4; nt++) {
            int ncol = n0 + wn + nt * 8 + tg * 2;
            float b0v = useb ? bias[ncol] : 0.f;
            float b1v = useb ? bias[ncol + 1] : 0.f;
            C[(size_t)r * ldc + ncol]           = acc[mt][nt][0] + b0v;
            C[(size_t)r * ldc + ncol + 1]       = acc[mt][nt][1] + b1v;
            C[(size_t)(r + 8) * ldc + ncol]     = acc[mt][nt][2] + b0v;
            C[(size_t)(r + 8) * ldc + ncol + 1] = acc[mt][nt][3] + b1v;
        }
    }
}

// ---------------- attention scores s_i, s_j ----------------
__global__ void si_sj_kernel(const float* __restrict__ hp, const float* __restrict__ attn_w,
                             float* __restrict__ si, float* __restrict__ sj) {
    int bn = blockIdx.x;
    int b = bn >> 9, n = bn & 511;
    const float* row = hp + (size_t)bn * cF;
    int t = threadIdx.x;  // 256
    for (int h = 0; h < cH; h++) {
        float v = row[h * cDH + t];
        float vi = v * attn_w[h * 2 * cDH + t];
        float vj = v * attn_w[h * 2 * cDH + cDH + t];
        float s1 = blockReduceF(vi, SumOp(), 0.f);
        float s2 = blockReduceF(vj, SumOp(), 0.f);
        if (t == 0) {
            si[((size_t)b * cH + h) * cN + n] = s1;
            sj[((size_t)b * cH + h) * cN + n] = s2;
        }
    }
}

// ---------------- per-row attention softmax ----------------
__global__ void attn_softmax(const float* __restrict__ si, const float* __restrict__ sj,
                             float* __restrict__ alpha) {
    int id = blockIdx.x;
    int i = id & 511, bh = id >> 9;
    float s_i = si[(size_t)bh * cN + i];
    const float* sjr = sj + (size_t)bh * cN;
    int t = threadIdx.x;
    float x0 = s_i + sjr[t];
    float x1 = s_i + sjr[t + 256];
    float e0 = x0 >= 0.f ? x0 : 0.2f * x0;
    float e1 = x1 >= 0.f ? x1 : 0.2f * x1;
    float m = blockReduceF(fmaxf(e0, e1), MaxOp(), -1e30f);
    float p0 = expf(e0 - m), p1 = expf(e1 - m);
    float s = blockReduceF(p0 + p1, SumOp(), 0.f);
    float inv = 1.f / s;
    float* arow = alpha + (size_t)id * cN;
    arow[t] = p0 * inv;
    arow[t + 256] = p1 * inv;
}

// ---------------- edge MLP ----------------
__global__ void edge_kernel(const float* __restrict__ pi, const float* __restrict__ pj,
                            const float* __restrict__ w2, const float* __restrict__ b2,
                            float* __restrict__ es) {
    __shared__ float pis[32][65];
    __shared__ float pjs[32][65];
    __shared__ float w2s[32];
    int b = blockIdx.z;
    int i0 = blockIdx.y * 64, j0 = blockIdx.x * 64;
    int tid = threadIdx.x;
    int tx = tid & 15, ty = tid >> 4;
    float acc[4][4] = {};
    for (int a0 = 0; a0 < cAH; a0 += 32) {
        for (int idx = tid; idx < 64 * 32; idx += 256) {
            int a = idx & 31, r = idx >> 5;
            pis[a][r] = pi[((size_t)(b * cN + i0 + r)) * cAH + a0 + a];
            pjs[a][r] = pj[((size_t)(b * cN + j0 + r)) * cAH + a0 + a];
        }
        if (tid < 32) w2s[tid] = w2[a0 + tid];
        __syncthreads();
#pragma unroll 8
        for (int a = 0; a < 32; a++) {
            float w = w2s[a];
            float pv[4], qv[4];
#pragma unroll
            for (int u = 0; u < 4; u++) pv[u] = pis[a][ty + 16 * u];
#pragma unroll
            for (int v = 0; v < 4; v++) qv[v] = pjs[a][tx + 16 * v];
#pragma unroll
            for (int u = 0; u < 4; u++)
#pragma unroll
                for (int v = 0; v < 4; v++)
                    acc[u][v] += fmaxf(pv[u] + qv[v], 0.f) * w;
        }
        __syncthreads();
    }
    float bb = b2[0];
#pragma unroll
    for (int u = 0; u < 4; u++)
#pragma unroll
        for (int v = 0; v < 4; v++)
            es[((size_t)b * cN + i0 + ty + 16 * u) * cN + j0 + tx + 16 * v] = acc[u][v] + bb;
}

// ---------------- flat softmax (scale 1/TEMP = 2) ----------------
__global__ void pmax_kernel(const float* __restrict__ es, float* __restrict__ part) {
    int b = blockIdx.y, seg = blockIdx.x;
    const float* p = es + (size_t)b * NN + seg * 2048;
    float m = -1e30f;
    for (int i = threadIdx.x; i < 2048; i += 256) m = fmaxf(m, p[i]);
    m = blockReduceF(m, MaxOp(), -1e30f);
    if (threadIdx.x == 0) part[b * 128 + seg] = m;
}

__global__ void psum_kernel(const float* __restrict__ es, const float* __restrict__ red,
                            float* __restrict__ part) {
    int b = blockIdx.y, seg = blockIdx.x;
    float m = red[b * 8 + 0];
    const float* p = es + (size_t)b * NN + seg * 2048;
    float s = 0.f;
    for (int i = threadIdx.x; i < 2048; i += 256) s += expf(2.f * (p[i] - m));
    s = blockReduceF(s, SumOp(), 0.f);
    if (threadIdx.x == 0) part[b * 128 + seg] = s;
}

__global__ void reduce_part(const float* __restrict__ part, float* __restrict__ red,
                            int mode, int slot) {
    int b = blockIdx.x;
    float v = part[b * 128 + threadIdx.x];
    v = mode ? blockReduceF(v, SumOp(), 0.f) : blockReduceF(v, MaxOp(), -1e30f);
    if (threadIdx.x == 0) red[b * 8 + slot] = v;
}

__global__ void softmax_write(const float* __restrict__ es, const float* __restrict__ red,
                              float* __restrict__ sm) {
    size_t i = (size_t)blockIdx.x * blockDim.x + threadIdx.x;
    int b = (int)(i / NN);
    float m = red[b * 8 + 0];
    float inv = 1.f / red[b * 8 + 1];
    sm[i] = expf(2.f * (es[i] - m)) * inv;
}

// ---------------- exact radix select ----------------
__global__ void sel_init() {
    int t = blockIdx.x * blockDim.x + threadIdx.x;
    if (t < cB * 256) g_hist[t] = 0;
    if (t < cB) { g_prefix[t] = 0; g_rank[t] = RANK_SEL; }
}

__global__ void sel_hist(const float* __restrict__ sm, int pass) {
    int b = blockIdx.y;
    int shift = 24 - 8 * pass;
    unsigned prefix = g_prefix[b];
    __shared__ unsigned hist[256];
    hist[threadIdx.x] = 0;
    __syncthreads();
    const unsigned* data = reinterpret_cast<const unsigned*>(sm) + (size_t)b * NN;
    int per = NN / gridDim.x;
    int base = blockIdx.x * per;
    for (int i = threadIdx.x; i < per; i += 256) {
        unsigned u = data[base + i];
        bool ok = (pass == 0) || ((u >> (shift + 8)) == (prefix >> (shift + 8)));
        int bin = ok ? (int)((u >> shift) & 255u) : -1;
        unsigned mask = __match_any_sync(0xffffffffu, bin);
        if (bin >= 0 && ((threadIdx.x & 31) == (__ffs(mask) - 1)))
            atomicAdd(&hist[bin], (unsigned)__popc(mask));
    }
    __syncthreads();
    if (hist[threadIdx.x]) atomicAdd(&g_hist[b * 256 + threadIdx.x], hist[threadIdx.x]);
}

__global__ void sel_step(float* __restrict__ red, int pass) {
    int b = blockIdx.x;
    int shift = 24 - 8 * pass;
    if (threadIdx.x == 0) {
        int r = g_rank[b];
        unsigned cum = 0;
        int sel = 0;
        for (int x = 0; x < 256; x++) {
            unsigned h = g_hist[b * 256 + x];
            if (cum + h > (unsigned)r) { sel = x; break; }
            cum += h;
        }
        g_rank[b] = r - (int)cum;
        unsigned p = g_prefix[b] | ((unsigned)sel << shift);
        g_prefix[b] = p;
        if (pass == 3) red[b * 8 + 2] = __uint_as_float(p);
    }
    __syncthreads();
    g_hist[b * 256 + threadIdx.x] = 0;
}

__global__ void csum_kernel(const float* __restrict__ sm, const float* __restrict__ red,
                            float* __restrict__ part) {
    int b = blockIdx.y, seg = blockIdx.x;
    float thr = red[b * 8 + 2];
    const float* p = sm + (size_t)b * NN + seg * 2048;
    float s = 0.f;
    for (int i = threadIdx.x; i < 2048; i += 256) {
        float v = p[i];
        if (v >= thr) s += v;
    }
    s = blockReduceF(s, SumOp(), 0.f);
    if (threadIdx.x == 0) part[b * 128 + seg] = s;
}

__global__ void adj_write(const float* __restrict__ sm, const float* __restrict__ red,
                          float* __restrict__ adj) {
    size_t i = (size_t)blockIdx.x * blockDim.x + threadIdx.x;
    int b = (int)(i / NN);
    float thr = red[b * 8 + 2];
    float inv = 1.f / (red[b * 8 + 3] + 1e-12f);
    float v = sm[i];
    adj[i] = (v >= thr) ? v * inv : 0.f;
}

// ---------------- batchnorm ----------------
__global__ void bn_stats(const float* __restrict__ h, int C, float* __restrict__ stats) {
    int c = blockIdx.x;
    double s = 0.0, s2 = 0.0;
    for (int r = threadIdx.x; r < cB * cN; r += blockDim.x) {
        double v = (double)h[(size_t)r * C + c];
        s += v;
        s2 += v * v;
    }
    s = blockReduceD(s);
    s2 = blockReduceD(s2);
    if (threadIdx.x == 0) {
        double m = s / (cB * cN);
        double var = s2 / (cB * cN) - m * m;
        stats[2 * c] = (float)m;
        stats[2 * c + 1] = (float)rsqrt(var + 1e-5);
    }
}

__global__ void bn_relu(const float* __restrict__ h, const float* __restrict__ stats,
                        const float* __restrict__ gamma, const float* __restrict__ beta,
                        float* __restrict__ out, int C) {
    size_t i = (size_t)blockIdx.x * blockDim.x + threadIdx.x;
    int c = (int)(i % C);
    float v = (h[i] - stats[2 * c]) * stats[2 * c + 1] * gamma[c] + beta[c];
    out[i] = fmaxf(v, 0.f);
}

// ---------------- final ----------------
__global__ void final_kernel(const float* __restrict__ g2, const float* __restrict__ stats,
                             const float* __restrict__ ga, const float* __restrict__ be,
                             const float* __restrict__ clsw, const float* __restrict__ clsb,
                             float* __restrict__ out) {
    int b = blockIdx.x, c = threadIdx.x;
    float m = stats[2 * c], is = stats[2 * c + 1], gg = ga[c], bb = be[c];
    float s = 0.f;
    for (int n = 0; n < cN; n++) {
        float v = g2[((size_t)(b * cN + n)) * cOUT + c];
        v = (v - m) * is * gg + bb;
        s += fmaxf(v, 0.f);
    }
    __shared__ float feat[cOUT];
    feat[c] = s * (1.f / cN);
    __syncthreads();
    if (c < cNC) {
        float o = clsb[c];
        for (int q = 0; q < cOUT; q++) o += feat[q] * clsw[c * cOUT + q];
        out[b * cNC + c] = o;
    }
}

// ---------------- launch ----------------
extern "C" void kernel_launch(void* const* d_in, const int* in_sizes, int n_in,
                              void* d_out, int out_size) {
    const float* x      = (const float*)d_in[0];
    const float* Wg     = (const float*)d_in[1];
    const float* attn_w = (const float*)d_in[2];
    const float* W1     = (const float*)d_in[3];
    const float* b1     = (const float*)d_in[4];
    const float* w2     = (const float*)d_in[5];
    const float* b2     = (const float*)d_in[6];
    const float* gc1_w  = (const float*)d_in[7];
    const float* gc1_b  = (const float*)d_in[8];
    const float* bn1g   = (const float*)d_in[9];
    const float* bn1b   = (const float*)d_in[10];
    const float* gc2_w  = (const float*)d_in[11];
    const float* gc2_b  = (const float*)d_in[12];
    const float* bn2g   = (const float*)d_in[13];
    const float* bn2b   = (const float*)d_in[14];
    const float* clsw   = (const float*)d_in[15];
    const float* clsb   = (const float*)d_in[16];

    float* buf = nullptr;
    cudaGetSymbolAddress((void**)&buf, g_buf);
    float* hp    = buf + OFF_HP;
    float* alpha = buf + OFF_ALPHA;
    float* nf    = buf + OFF_NF;
    float* pi    = buf + OFF_PI;
    float* es    = buf + OFF_ES;
    float* sm    = buf + OFF_SM;
    float* adj   = buf + OFF_ADJ;
    float* h1    = buf + OFF_H1;
    float* g1    = buf + OFF_G1;
    float* h2    = buf + OFF_H2;
    float* g2    = buf + OFF_G2;
    float* si    = buf + OFF_SI;
    float* sj    = buf + OFF_SJ;
    float* part  = buf + OFF_PART;
    float* red   = buf + OFF_RED;
    float* bn1s  = buf + OFF_BN1;
    float* bn2s  = buf + OFF_BN2;
    float* pj    = buf + OFF_PJ;

    typedef long long ll;

    // 1) hp = x @ Wg^T
    gemm_tc<<<dim3(cF / 64, (cB * cN) / 64, 1), 128>>>(
        x, cF, 0, 0, Wg, cF, 0, 0, hp, cF, 0, 0,
        cB * cN, cF, cF, 1, nullptr, 0, 1);
    // 2) s_i, s_j
    si_sj_kernel<<<cB * cN, 256>>>(hp, attn_w, si, sj);
    // 3) attention softmax
    attn_softmax<<<cB * cH * cN, 256>>>(si, sj, alpha);
    // 4) node_feats = alpha @ hp (batched b,h)
    gemm_tc<<<dim3(cDH / 64, cN / 64, cB * cH), 128>>>(
        alpha, cN, (ll)cH * NN, (ll)NN,
        hp, cF, (ll)cN * cF, (ll)cDH,
        nf, cF, (ll)cN * cF, (ll)cDH,
        cN, cDH, cN, cH, nullptr, 0, 0);
    // 5) pi/pj fused (grid.z = 2)
    gemm_tc<<<dim3(cAH / 64, (cB * cN) / 64, 2), 128>>>(
        nf, cF, 0, 0,
        W1, 2 * cF, 0, (ll)cF,
        pi, cAH, 0, (ll)cB * cN * cAH,
        cB * cN, cAH, cF, 2, b1, 1, 1);
    // 6) edge scores
    edge_kernel<<<dim3(cN / 64, cN / 64, cB), 256>>>(pi, pj, w2, b2, es);
    // 7) flat softmax
    pmax_kernel<<<dim3(128, cB), 256>>>(es, part);
    reduce_part<<<cB, 128>>>(part, red, 0, 0);
    psum_kernel<<<dim3(128, cB), 256>>>(es, red, part);
    reduce_part<<<cB, 128>>>(part, red, 1, 1);
    softmax_write<<<(cB * NN) / 256, 256>>>(es, red, sm);
    // 8) exact order statistic
    sel_init<<<2, 256>>>();
    for (int p = 0; p < 4; p++) {
        sel_hist<<<dim3(64, cB), 256>>>(sm, p);
        sel_step<<<cB, 256>>>(red, p);
    }
    // 9) kept-sum + adjacency
    csum_kernel<<<dim3(128, cB), 256>>>(sm, red, part);
    reduce_part<<<cB, 128>>>(part, red, 1, 3);
    adj_write<<<(cB * NN) / 256, 256>>>(sm, red, adj);
    // 10) h1 = adj @ nf
    gemm_tc<<<dim3(cF / 64, cN / 64, cB), 128>>>(
        adj, cN, (ll)NN, 0,
        nf, cF, (ll)cN * cF, 0,
        h1, cF, (ll)cN * cF, 0,
        cN, cF, cN, 1, nullptr, 0, 0);
    // 11) g1 = h1 @ gc1_w^T + b ; bn1 ; relu
    gemm_tc<<<dim3(cHID / 64, (cB * cN) / 64, 1), 128>>>(
        h1, cF, 0, 0, gc1_w, cF, 0, 0, g1, cHID, 0, 0,
        cB * cN, cHID, cF, 1, gc1_b, 1, 1);
    bn_stats<<<cHID, 256>>>(g1, cHID, bn1s);
    bn_relu<<<(cB * cN * cHID) / 256, 256>>>(g1, bn1s, bn1g, bn1b, g1, cHID);
    // 12) h2 = adj @ g1
    gemm_tc<<<dim3(cHID / 64, cN / 64, cB), 128>>>(
        adj, cN, (ll)NN, 0,
        g1, cHID, (ll)cN * cHID, 0,
        h2, cHID, (ll)cN * cHID, 0,
        cN, cHID, cN, 1, nullptr, 0, 0);
    // 13) g2 = h2 @ gc2_w^T + b ; bn2 stats
    gemm_tc<<<dim3(cOUT / 64, (cB * cN) / 64, 1), 128>>>(
        h2, cHID, 0, 0, gc2_w, cHID, 0, 0, g2, cOUT, 0, 0,
        cB * cN, cOUT, cHID, 1, gc2_b, 1, 1);
    bn_stats<<<cOUT, 256>>>(g2, cOUT, bn2s);
    // 14) final
    final_kernel<<<cB, 128>>>(g2, bn2s, bn2g, bn2b, clsw, clsb, (float*)d_out);
}

// round 4
// speedup vs baseline: 3.4153x; 1.0058x over previous
#include <cuda_runtime.h>
#include <math.h>

#define DEV_INLINE __device__ __forceinline__

// ---------------- problem constants ----------------
constexpr int cB = 2, cN = 512, cF = 1024, cH = 4, cDH = 256;
constexpr int cAH = 256, cHID = 512, cOUT = 128, cNC = 10;
constexpr int NN = cN * cN;               // 262144
constexpr int KSEL = 209715;              // int(0.8 * 512 * 512)
constexpr int RANK_SEL = NN - KSEL;       // 52429

// ---------------- scratch layout ----------------
constexpr size_t OFF_HP    = 0;
constexpr size_t OFF_ALPHA = OFF_HP    + (size_t)cB * cN * cF;
constexpr size_t OFF_NF    = OFF_ALPHA + (size_t)cB * cH * cN * cN;
constexpr size_t OFF_PI    = OFF_NF    + (size_t)cB * cN * cF;
constexpr size_t OFF_PJ    = OFF_PI    + (size_t)cB * cN * cAH;
constexpr size_t OFF_ES    = OFF_PJ    + (size_t)cB * cN * cAH;
constexpr size_t OFF_ADJ   = OFF_ES    + (size_t)cB * NN;
constexpr size_t OFF_H1    = OFF_ADJ   + (size_t)cB * NN;
constexpr size_t OFF_G1    = OFF_H1    + (size_t)cB * cN * cF;
constexpr size_t OFF_H2    = OFF_G1    + (size_t)cB * cN * cHID;
constexpr size_t OFF_G2    = OFF_H2    + (size_t)cB * cN * cHID;
constexpr size_t OFF_SI    = OFF_G2    + (size_t)cB * cN * cOUT;
constexpr size_t OFF_SJ    = OFF_SI    + (size_t)cB * cH * cN;
constexpr size_t OFF_PART  = OFF_SJ    + (size_t)cB * cH * cN;
constexpr size_t OFF_RED   = OFF_PART  + (size_t)cB * 256;
constexpr size_t OFF_BN1   = OFF_RED   + (size_t)cB * 8;
constexpr size_t OFF_BN2   = OFF_BN1   + (size_t)2 * cHID;
constexpr size_t BUF_TOTAL = OFF_BN2   + (size_t)2 * cOUT;

__device__ float    g_buf[BUF_TOTAL];
__device__ unsigned g_hist[cB * 256];
__device__ unsigned g_prefix[cB];
__device__ int      g_rank[cB];
__device__ unsigned g_maxkey[cB];

// ---------------- order-preserving float<->key transform ----------------
DEV_INLINE unsigned okey(float f) {
    int u = __float_as_int(f);
    return (unsigned)(u ^ ((u >> 31) | 0x80000000));
}
DEV_INLINE float okey_dec(unsigned k) {
    unsigned u = (k & 0x80000000u) ? (k ^ 0x80000000u) : ~k;
    return __uint_as_float(u);
}

// ---------------- reductions ----------------
struct SumOp { DEV_INLINE float operator()(float a, float b) const { return a + b; } };
struct MaxOp { DEV_INLINE float operator()(float a, float b) const { return fmaxf(a, b); } };

template <typename Op>
DEV_INLINE float blockReduceF(float v, Op op, float init) {
    __shared__ float sh[32];
    __syncthreads();
    int lane = threadIdx.x & 31, w = threadIdx.x >> 5;
#pragma unroll
    for (int o = 16; o; o >>= 1) v = op(v, __shfl_down_sync(0xffffffffu, v, o));
    if (lane == 0) sh[w] = v;
    __syncthreads();
    int nw = (blockDim.x + 31) >> 5;
    v = (threadIdx.x < nw) ? sh[threadIdx.x] : init;
    if (w == 0) {
#pragma unroll
        for (int o = 16; o; o >>= 1) v = op(v, __shfl_down_sync(0xffffffffu, v, o));
        if (lane == 0) sh[0] = v;
    }
    __syncthreads();
    return sh[0];
}

DEV_INLINE double blockReduceD(double v) {
    __shared__ double shd[32];
    __syncthreads();
    int lane = threadIdx.x & 31, w = threadIdx.x >> 5;
#pragma unroll
    for (int o = 16; o; o >>= 1) v += __shfl_down_sync(0xffffffffu, v, o);
    if (lane == 0) shd[w] = v;
    __syncthreads();
    int nw = (blockDim.x + 31) >> 5;
    v = (threadIdx.x < nw) ? shd[threadIdx.x] : 0.0;
    if (w == 0) {
#pragma unroll
        for (int o = 16; o; o >>= 1) v += __shfl_down_sync(0xffffffffu, v, o);
        if (lane == 0) shd[0] = v;
    }
    __syncthreads();
    return shd[0];
}

// ---------------- bf16 split helpers ----------------
DEV_INLINE unsigned pack_bf2(float f_even, float f_odd) {
    unsigned r;
    asm("cvt.rn.bf16x2.f32 %0, %1, %2;" : "=r"(r) : "f"(f_odd), "f"(f_even));
    return r;
}
DEV_INLINE void split2(float f0, float f1, unsigned& hi, unsigned& lo) {
    hi = pack_bf2(f0, f1);
    float h0 = __uint_as_float(hi << 16);
    float h1 = __uint_as_float(hi & 0xFFFF0000u);
    lo = pack_bf2(f0 - h0, f1 - h1);
}

DEV_INLINE void mma_bf16(float* c, unsigned a0, unsigned a1, unsigned a2, unsigned a3,
                         unsigned b0, unsigned b1) {
    asm volatile(
        "mma.sync.aligned.m16n8k16.row.col.f32.bf16.bf16.f32 "
        "{%0,%1,%2,%3}, {%4,%5,%6,%7}, {%8,%9}, {%0,%1,%2,%3};\n"
        : "+f"(c[0]), "+f"(c[1]), "+f"(c[2]), "+f"(c[3])
        : "r"(a0), "r"(a1), "r"(a2), "r"(a3), "r"(b0), "r"(b1));
}

// ---------------- tensor-core GEMM (3xBF16 split, near-fp32 accuracy) -------
// C[m,n] = sum_k A[m,k] * B'[k,n]  where B' = B[n,k] if b_nk else B[k,n].
// 64x64 tile, ktile 32, 256 threads (8 warps, 2x4 layout, warp tile 32x16).
// smem: uint2 {hi,lo} packed bf16x2 k-pairs; register global prefetch.
constexpr int SMP2 = 68;

__global__ __launch_bounds__(256) void gemm_tc(
    const float* __restrict__ A, int lda, long long sA1, long long sA2,
    const float* __restrict__ B, int ldb, long long sB1, long long sB2,
    float* __restrict__ C, int ldc, long long sC1, long long sC2,
    int M, int Nd, int K, int HH,
    const float* __restrict__ bias, int bias_z, int b_nk) {
    __shared__ uint2 As[16][SMP2];
    __shared__ uint2 Bs[16][SMP2];
    int z = blockIdx.z, z1 = z / HH, z2 = z % HH;
    A += (size_t)z1 * sA1 + (size_t)z2 * sA2;
    B += (size_t)z1 * sB1 + (size_t)z2 * sB2;
    C += (size_t)z1 * sC1 + (size_t)z2 * sC2;
    int tid = threadIdx.x;
    int m0 = blockIdx.y * 64, n0 = blockIdx.x * 64;
    int lane = tid & 31, wid = tid >> 5;
    int wm = (wid >> 2) * 32, wn = (wid & 3) * 16;
    int tg = lane & 3, gp = lane >> 2;
    float acc[2][2][4] = {};
    const float* Ag = A + (size_t)m0 * lda;
    const float* Bg_nt = B + (size_t)n0 * ldb;

    float4 pa[2], pb[2];

    auto loadA = [&](int k0) {
#pragma unroll
        for (int it = 0; it < 2; it++) {
            int idx = tid + it * 256;
            int r = idx >> 3, c4 = idx & 7;
            pa[it] = *reinterpret_cast<const float4*>(Ag + (size_t)r * lda + k0 + c4 * 4);
        }
    };
    auto storeA = [&]() {
#pragma unroll
        for (int it = 0; it < 2; it++) {
            int idx = tid + it * 256;
            int r = idx >> 3, kp = (idx & 7) * 2;
            unsigned h0, l0, h1, l1;
            split2(pa[it].x, pa[it].y, h0, l0);
            split2(pa[it].z, pa[it].w, h1, l1);
            As[kp][r] = make_uint2(h0, l0);
            As[kp + 1][r] = make_uint2(h1, l1);
        }
    };
    auto loadB = [&](int k0) {
        if (b_nk) {
#pragma unroll
            for (int it = 0; it < 2; it++) {
                int idx = tid + it * 256;
                int r = idx >> 3, c4 = idx & 7;
                pb[it] = *reinterpret_cast<const float4*>(Bg_nt + (size_t)r * ldb + k0 + c4 * 4);
            }
        } else {
            int kp = tid >> 4, nc = (tid & 15) * 4;
            pb[0] = *reinterpret_cast<const float4*>(B + (size_t)(k0 + 2 * kp) * ldb + n0 + nc);
            pb[1] = *reinterpret_cast<const float4*>(B + (size_t)(k0 + 2 * kp + 1) * ldb + n0 + nc);
        }
    };
    auto storeB = [&]() {
        if (b_nk) {
#pragma unroll
            for (int it = 0; it < 2; it++) {
                int idx = tid + it * 256;
                int r = idx >> 3, kp = (idx & 7) * 2;
                unsigned h0, l0, h1, l1;
                split2(pb[it].x, pb[it].y, h0, l0);
                split2(pb[it].z, pb[it].w, h1, l1);
                Bs[kp][r] = make_uint2(h0, l0);
                Bs[kp + 1][r] = make_uint2(h1, l1);
            }
        } else {
            int kp = tid >> 4, nc = (tid & 15) * 4;
            float fe[4] = {pb[0].x, pb[0].y, pb[0].z, pb[0].w};
            float fo[4] = {pb[1].x, pb[1].y, pb[1].z, pb[1].w};
#pragma unroll
            for (int j = 0; j < 4; j++) {
                unsigned h, l;
                split2(fe[j], fo[j], h, l);
                Bs[kp][nc + j] = make_uint2(h, l);
            }
        }
    };

    loadA(0);
    loadB(0);
    for (int k0 = 0; k0 < K; k0 += 32) {
        storeA();
        storeB();
        __syncthreads();
        if (k0 + 32 < K) { loadA(k0 + 32); loadB(k0 + 32); }
#pragma unroll
        for (int ks = 0; ks < 16; ks += 8) {
            uint2 af[2][4], bf[2][2];
#pragma unroll
            for (int mt = 0; mt < 2; mt++) {
                int m = wm + mt * 16 + gp;
                af[mt][0] = As[ks + tg][m];     af[mt][1] = As[ks + tg][m + 8];
                af[mt][2] = As[ks + tg + 4][m]; af[mt][3] = As[ks + tg + 4][m + 8];
            }
#pragma unroll
            for (int nt = 0; nt < 2; nt++) {
                int n = wn + nt * 8 + gp;
                bf[nt][0] = Bs[ks + tg][n];
                bf[nt][1] = Bs[ks + tg + 4][n];
            }
            // hi*hi
#pragma unroll
            for (int nt = 0; nt < 2; nt++)
#pragma unroll
                for (int mt = 0; mt < 2; mt++)
                    mma_bf16(acc[mt][nt], af[mt][0].x, af[mt][1].x, af[mt][2].x, af[mt][3].x,
                             bf[nt][0].x, bf[nt][1].x);
            // lo*hi
#pragma unroll
            for (int nt = 0; nt < 2; nt++)
#pragma unroll
                for (int mt = 0; mt < 2; mt++)
                    mma_bf16(acc[mt][nt], af[mt][0].y, af[mt][1].y, af[mt][2].y, af[mt][3].y,
                             bf[nt][0].x, bf[nt][1].x);
            // hi*lo
#pragma unroll
            for (int nt = 0; nt < 2; nt++)
#pragma unroll
                for (int mt = 0; mt < 2; mt++)
                    mma_bf16(acc[mt][nt], af[mt][0].x, af[mt][1].x, af[mt][2].x, af[mt][3].x,
                             bf[nt][0].y, bf[nt][1].y);
        }
        __syncthreads();
    }
    bool useb = (bias != nullptr) && (z2 < bias_z);
#pragma unroll
    for (int mt = 0; mt < 2; mt++) {
        int r = m0 + wm + mt * 16 + gp;
#pragma unroll
        for (int nt = 0; nt < 2; nt++) {
            int ncol = n0 + wn + nt * 8 + tg * 2;
            float b0v = useb ? bias[ncol] : 0.f;
            float b1v = useb ? bias[ncol + 1] : 0.f;
            C[(size_t)r * ldc + ncol]           = acc[mt][nt][0] + b0v;
            C[(size_t)r * ldc + ncol + 1]       = acc[mt][nt][1] + b1v;
            C[(size_t)(r + 8) * ldc + ncol]     = acc[mt][nt][2] + b0v;
            C[(size_t)(r + 8) * ldc + ncol + 1] = acc[mt][nt][3] + b1v;
        }
    }
}

// ---------------- attention scores s_i, s_j ----------------
__global__ void si_sj_kernel(const float* __restrict__ hp, const float* __restrict__ attn_w,
                             float* __restrict__ si, float* __restrict__ sj) {
    int bn = blockIdx.x;
    int b = bn >> 9, n = bn & 511;
    const float* row = hp + (size_t)bn * cF;
    int t = threadIdx.x;  // 256
    for (int h = 0; h < cH; h++) {
        float v = row[h * cDH + t];
        float vi = v * attn_w[h * 2 * cDH + t];
        float vj = v * attn_w[h * 2 * cDH + cDH + t];
        float s1 = blockReduceF(vi, SumOp(), 0.f);
        float s2 = blockReduceF(vj, SumOp(), 0.f);
        if (t == 0) {
            si[((size_t)b * cH + h) * cN + n] = s1;
            sj[((size_t)b * cH + h) * cN + n] = s2;
        }
    }
}

// ---------------- per-row attention softmax ----------------
__global__ void attn_softmax(const float* __restrict__ si, const float* __restrict__ sj,
                             float* __restrict__ alpha) {
    int id = blockIdx.x;
    int i = id & 511, bh = id >> 9;
    float s_i = si[(size_t)bh * cN + i];
    const float* sjr = sj + (size_t)bh * cN;
    int t = threadIdx.x;
    float x0 = s_i + sjr[t];
    float x1 = s_i + sjr[t + 256];
    float e0 = x0 >= 0.f ? x0 : 0.2f * x0;
    float e1 = x1 >= 0.f ? x1 : 0.2f * x1;
    float m = blockReduceF(fmaxf(e0, e1), MaxOp(), -1e30f);
    float p0 = expf(e0 - m), p1 = expf(e1 - m);
    float s = blockReduceF(p0 + p1, SumOp(), 0.f);
    float inv = 1.f / s;
    float* arow = alpha + (size_t)id * cN;
    arow[t] = p0 * inv;
    arow[t + 256] = p1 * inv;
}

// ---------------- edge MLP + global-max epilogue ----------------
__global__ void edge_kernel(const float* __restrict__ pi, const float* __restrict__ pj,
                            const float* __restrict__ w2, const float* __restrict__ b2,
                            float* __restrict__ es) {
    __shared__ float pis[32][65];
    __shared__ float pjs[32][65];
    __shared__ float w2s[32];
    int b = blockIdx.z;
    int i0 = blockIdx.y * 64, j0 = blockIdx.x * 64;
    int tid = threadIdx.x;
    int tx = tid & 15, ty = tid >> 4;
    float acc[4][4] = {};
    for (int a0 = 0; a0 < cAH; a0 += 32) {
        for (int idx = tid; idx < 64 * 32; idx += 256) {
            int a = idx & 31, r = idx >> 5;
            pis[a][r] = pi[((size_t)(b * cN + i0 + r)) * cAH + a0 + a];
            pjs[a][r] = pj[((size_t)(b * cN + j0 + r)) * cAH + a0 + a];
        }
        if (tid < 32) w2s[tid] = w2[a0 + tid];
        __syncthreads();
#pragma unroll 8
        for (int a = 0; a < 32; a++) {
            float w = w2s[a];
            float pv[4], qv[4];
#pragma unroll
            for (int u = 0; u < 4; u++) pv[u] = pis[a][ty + 16 * u];
#pragma unroll
            for (int v = 0; v < 4; v++) qv[v] = pjs[a][tx + 16 * v];
#pragma unroll
            for (int u = 0; u < 4; u++)
#pragma unroll
                for (int v = 0; v < 4; v++)
                    acc[u][v] += fmaxf(pv[u] + qv[v], 0.f) * w;
        }
        __syncthreads();
    }
    float bb = b2[0];
    float lmax = -1e30f;
#pragma unroll
    for (int u = 0; u < 4; u++)
#pragma unroll
        for (int v = 0; v < 4; v++) {
            float val = acc[u][v] + bb;
            es[((size_t)b * cN + i0 + ty + 16 * u) * cN + j0 + tx + 16 * v] = val;
            lmax = fmaxf(lmax, val);
        }
    lmax = blockReduceF(lmax, MaxOp(), -1e30f);
    if (tid == 0) atomicMax(&g_maxkey[b], okey(lmax));
}

// ---------------- exact radix select over es (order-keys) ----------------
__global__ void sel_init() {
    int t = blockIdx.x * blockDim.x + threadIdx.x;
    if (t < cB * 256) g_hist[t] = 0;
    if (t < cB) { g_prefix[t] = 0; g_rank[t] = RANK_SEL; g_maxkey[t] = 0; }
}

__global__ void sel_hist(const float* __restrict__ es, int pass) {
    int b = blockIdx.y;
    int shift = 24 - 8 * pass;
    unsigned prefix = g_prefix[b];
    __shared__ unsigned hist[256];
    hist[threadIdx.x] = 0;
    __syncthreads();
    const float* data = es + (size_t)b * NN;
    int per = NN / gridDim.x;
    int base = blockIdx.x * per;
    for (int i = threadIdx.x; i < per; i += 256) {
        unsigned u = okey(data[base + i]);
        bool ok = (pass == 0) || ((u >> (shift + 8)) == (prefix >> (shift + 8)));
        int bin = ok ? (int)((u >> shift) & 255u) : -1;
        unsigned mask = __match_any_sync(0xffffffffu, bin);
        if (bin >= 0 && ((threadIdx.x & 31) == (__ffs(mask) - 1)))
            atomicAdd(&hist[bin], (unsigned)__popc(mask));
    }
    __syncthreads();
    if (hist[threadIdx.x]) atomicAdd(&g_hist[b * 256 + threadIdx.x], hist[threadIdx.x]);
}

__global__ void sel_step(float* __restrict__ red, int pass) {
    int b = blockIdx.x;
    int shift = 24 - 8 * pass;
    if (threadIdx.x == 0) {
        int r = g_rank[b];
        unsigned cum = 0;
        int sel = 0;
        for (int x = 0; x < 256; x++) {
            unsigned h = g_hist[b * 256 + x];
            if (cum + h > (unsigned)r) { sel = x; break; }
            cum += h;
        }
        g_rank[b] = r - (int)cum;
        unsigned p = g_prefix[b] | ((unsigned)sel << shift);
        g_prefix[b] = p;
        if (pass == 3) red[b * 8 + 2] = __uint_as_float(p);  // threshold KEY
    }
    __syncthreads();
    g_hist[b * 256 + threadIdx.x] = 0;
}

// ---------------- kept-sum + full-sum of exp(2(e-m)) in one pass ------------
__global__ void csum2_kernel(const float* __restrict__ es, const float* __restrict__ red,
                             float* __restrict__ part) {
    int b = blockIdx.y, seg = blockIdx.x;
    unsigned thr = __float_as_uint(red[b * 8 + 2]);
    float m = okey_dec(g_maxkey[b]);
    const float* p = es + (size_t)b * NN + seg * 2048;
    float sk = 0.f, sz = 0.f;
    for (int i = threadIdx.x; i < 2048; i += 256) {
        float v = p[i];
        float e = expf(2.f * (v - m));
        sz += e;
        if (okey(v) >= thr) sk += e;
    }
    sk = blockReduceF(sk, SumOp(), 0.f);
    sz = blockReduceF(sz, SumOp(), 0.f);
    if (threadIdx.x == 0) {
        part[b * 256 + seg] = sk;
        part[b * 256 + 128 + seg] = sz;
    }
}

__global__ void reduce2_kernel(const float* __restrict__ part, float* __restrict__ red) {
    int b = blockIdx.x;
    float v1 = part[b * 256 + threadIdx.x];        // 128 threads
    float v2 = part[b * 256 + 128 + threadIdx.x];
    v1 = blockReduceF(v1, SumOp(), 0.f);
    v2 = blockReduceF(v2, SumOp(), 0.f);
    if (threadIdx.x == 0) {
        red[b * 8 + 3] = v1;  // S_kept
        red[b * 8 + 4] = v2;  // Z
    }
}

__global__ void adj_write(const float* __restrict__ es, const float* __restrict__ red,
                          float* __restrict__ adj) {
    size_t i = (size_t)blockIdx.x * blockDim.x + threadIdx.x;
    int b = (int)(i / NN);
    unsigned thr = __float_as_uint(red[b * 8 + 2]);
    float m = okey_dec(g_maxkey[b]);
    float inv = 1.f / (red[b * 8 + 3] + red[b * 8 + 4] * 1e-12f);
    float v = es[i];
    adj[i] = (okey(v) >= thr) ? expf(2.f * (v - m)) * inv : 0.f;
}

// ---------------- batchnorm ----------------
__global__ void bn_stats(const float* __restrict__ h, int C, float* __restrict__ stats) {
    int c = blockIdx.x;
    double s = 0.0, s2 = 0.0;
    for (int r = threadIdx.x; r < cB * cN; r += blockDim.x) {
        double v = (double)h[(size_t)r * C + c];
        s += v;
        s2 += v * v;
    }
    s = blockReduceD(s);
    s2 = blockReduceD(s2);
    if (threadIdx.x == 0) {
        double m = s / (cB * cN);
        double var = s2 / (cB * cN) - m * m;
        stats[2 * c] = (float)m;
        stats[2 * c + 1] = (float)rsqrt(var + 1e-5);
    }
}

__global__ void bn_relu(const float* __restrict__ h, const float* __restrict__ stats,
                        const float* __restrict__ gamma, const float* __restrict__ beta,
                        float* __restrict__ out, int C) {
    size_t i = (size_t)blockIdx.x * blockDim.x + threadIdx.x;
    int c = (int)(i % C);
    float v = (h[i] - stats[2 * c]) * stats[2 * c + 1] * gamma[c] + beta[c];
    out[i] = fmaxf(v, 0.f);
}

// ---------------- final ----------------
__global__ void final_kernel(const float* __restrict__ g2, const float* __restrict__ stats,
                             const float* __restrict__ ga, const float* __restrict__ be,
                             const float* __restrict__ clsw, const float* __restrict__ clsb,
                             float* __restrict__ out) {
    int b = blockIdx.x, c = threadIdx.x;
    float m = stats[2 * c], is = stats[2 * c + 1], gg = ga[c], bb = be[c];
    float s = 0.f;
    for (int n = 0; n < cN; n++) {
        float v = g2[((size_t)(b * cN + n)) * cOUT + c];
        v = (v - m) * is * gg + bb;
        s += fmaxf(v, 0.f);
    }
    __shared__ float feat[cOUT];
    feat[c] = s * (1.f / cN);
    __syncthreads();
    if (c < cNC) {
        float o = clsb[c];
        for (int q = 0; q < cOUT; q++) o += feat[q] * clsw[c * cOUT + q];
        out[b * cNC + c] = o;
    }
}

// ---------------- launch ----------------
extern "C" void kernel_launch(void* const* d_in, const int* in_sizes, int n_in,
                              void* d_out, int out_size) {
    const float* x      = (const float*)d_in[0];
    const float* Wg     = (const float*)d_in[1];
    const float* attn_w = (const float*)d_in[2];
    const float* W1     = (const float*)d_in[3];
    const float* b1     = (const float*)d_in[4];
    const float* w2     = (const float*)d_in[5];
    const float* b2     = (const float*)d_in[6];
    const float* gc1_w  = (const float*)d_in[7];
    const float* gc1_b  = (const float*)d_in[8];
    const float* bn1g   = (const float*)d_in[9];
    const float* bn1b   = (const float*)d_in[10];
    const float* gc2_w  = (const float*)d_in[11];
    const float* gc2_b  = (const float*)d_in[12];
    const float* bn2g   = (const float*)d_in[13];
    const float* bn2b   = (const float*)d_in[14];
    const float* clsw   = (const float*)d_in[15];
    const float* clsb   = (const float*)d_in[16];

    float* buf = nullptr;
    cudaGetSymbolAddress((void**)&buf, g_buf);
    float* hp    = buf + OFF_HP;
    float* alpha = buf + OFF_ALPHA;
    float* nf    = buf + OFF_NF;
    float* pi    = buf + OFF_PI;
    float* pj    = buf + OFF_PJ;
    float* es    = buf + OFF_ES;
    float* adj   = buf + OFF_ADJ;
    float* h1    = buf + OFF_H1;
    float* g1    = buf + OFF_G1;
    float* h2    = buf + OFF_H2;
    float* g2    = buf + OFF_G2;
    float* si    = buf + OFF_SI;
    float* sj    = buf + OFF_SJ;
    float* part  = buf + OFF_PART;
    float* red   = buf + OFF_RED;
    float* bn1s  = buf + OFF_BN1;
    float* bn2s  = buf + OFF_BN2;

    typedef long long ll;

    // 0) init select state + max-keys (must precede edge_kernel)
    sel_init<<<2, 256>>>();
    // 1) hp = x @ Wg^T
    gemm_tc<<<dim3(cF / 64, (cB * cN) / 64, 1), 256>>>(
        x, cF, 0, 0, Wg, cF, 0, 0, hp, cF, 0, 0,
        cB * cN, cF, cF, 1, nullptr, 0, 1);
    // 2) s_i, s_j
    si_sj_kernel<<<cB * cN, 256>>>(hp, attn_w, si, sj);
    // 3) attention softmax
    attn_softmax<<<cB * cH * cN, 256>>>(si, sj, alpha);
    // 4) node_feats = alpha @ hp (batched b,h)
    gemm_tc<<<dim3(cDH / 64, cN / 64, cB * cH), 256>>>(
        alpha, cN, (ll)cH * NN, (ll)NN,
        hp, cF, (ll)cN * cF, (ll)cDH,
        nf, cF, (ll)cN * cF, (ll)cDH,
        cN, cDH, cN, cH, nullptr, 0, 0);
    // 5) pi/pj fused (grid.z = 2)
    gemm_tc<<<dim3(cAH / 64, (cB * cN) / 64, 2), 256>>>(
        nf, cF, 0, 0,
        W1, 2 * cF, 0, (ll)cF,
        pi, cAH, 0, (ll)cB * cN * cAH,
        cB * cN, cAH, cF, 2, b1, 1, 1);
    // 6) edge scores + per-batch max (atomic)
    edge_kernel<<<dim3(cN / 64, cN / 64, cB), 256>>>(pi, pj, w2, b2, es);
    // 7) exact order statistic directly on es (4-pass radix on order-keys)
    for (int p = 0; p < 4; p++) {
        sel_hist<<<dim3(64, cB), 256>>>(es, p);
        sel_step<<<cB, 256>>>(red, p);
    }
    // 8) kept-sum + Z in one pass; adjacency write (softmax normalizer cancels)
    csum2_kernel<<<dim3(128, cB), 256>>>(es, red, part);
    reduce2_kernel<<<cB, 128>>>(part, red);
    adj_write<<<(cB * NN) / 256, 256>>>(es, red, adj);
    // 9) h1 = adj @ nf
    gemm_tc<<<dim3(cF / 64, cN / 64, cB), 256>>>(
        adj, cN, (ll)NN, 0,
        nf, cF, (ll)cN * cF, 0,
        h1, cF, (ll)cN * cF, 0,
        cN, cF, cN, 1, nullptr, 0, 0);
    // 10) g1 = h1 @ gc1_w^T + b ; bn1 ; relu
    gemm_tc<<<dim3(cHID / 64, (cB * cN) / 64, 1), 256>>>(
        h1, cF, 0, 0, gc1_w, cF, 0, 0, g1, cHID, 0, 0,
        cB * cN, cHID, cF, 1, gc1_b, 1, 1);
    bn_stats<<<cHID, 256>>>(g1, cHID, bn1s);
    bn_relu<<<(cB * cN * cHID) / 256, 256>>>(g1, bn1s, bn1g, bn1b, g1, cHID);
    // 11) h2 = adj @ g1
    gemm_tc<<<dim3(cHID / 64, cN / 64, cB), 256>>>(
        adj, cN, (ll)NN, 0,
        g1, cHID, (ll)cN * cHID, 0,
        h2, cHID, (ll)cN * cHID, 0,
        cN, cHID, cN, 1, nullptr, 0, 0);
    // 12) g2 = h2 @ gc2_w^T + b ; bn2 stats
    gemm_tc<<<dim3(cOUT / 64, (cB * cN) / 64, 1), 256>>>(
        h2, cHID, 0, 0, gc2_w, cHID, 0, 0, g2, cOUT, 0, 0,
        cB * cN, cOUT, cHID, 1, gc2_b, 1, 1);
    bn_stats<<<cOUT, 256>>>(g2, cOUT, bn2s);
    // 13) final
    final_kernel<<<cB, 128>>>(g2, bn2s, bn2g, bn2b, clsw, clsb, (float*)d_out);
}